// round 6
// baseline (speedup 1.0000x reference)
#include <cuda_runtime.h>
#include <math.h>

// ---------------------------------------------------------------------------
// Decoder layer: B=2, N=2048, D=512, H=8, Dh=64, FF=2048
//   x = LN1( selfAttn(x) + x )
//   x = LN2( crossAttn(x, enc) + x )
//   x = LN3( FF(x) + x )
// fp32 throughout for round-1 correctness.
// ---------------------------------------------------------------------------

#define NSEQ   2048
#define BATCH  2
#define DMODEL 512
#define NHEAD  8
#define DHEAD  64
#define DFF    2048
#define TKN    (BATCH * NSEQ)   // 4096 tokens

// ---------------- device scratch (no allocations allowed) ------------------
__device__ float g_q   [TKN * DMODEL];
__device__ float g_k   [TKN * DMODEL];
__device__ float g_v   [TKN * DMODEL];
__device__ float g_attn[TKN * DMODEL];
__device__ float g_t0  [TKN * DMODEL];
__device__ float g_x1  [TKN * DMODEL];
__device__ float g_x2  [TKN * DMODEL];
__device__ float g_ff  [TKN * DFF];

enum { EPI_BIAS = 0, EPI_BIAS_RES = 1, EPI_BIAS_GELU = 2 };

// ---------------------------------------------------------------------------
// Tiled SGEMM: C[M,N] = A[M,K] @ W[K,N] + bias (+res / gelu epilogue)
// BM/TM * BN/TN = 256 threads. As stored K-major-transposed for float4 frags.
// ---------------------------------------------------------------------------
template<int BM, int BN, int BK, int TM, int TN, int EPI>
__global__ void __launch_bounds__((BM / TM) * (BN / TN))
sgemm_k(const float* __restrict__ A, const float* __restrict__ W,
        const float* __restrict__ bias, const float* __restrict__ res,
        float* __restrict__ C, int M, int N, int K)
{
    constexpr int NT = (BM / TM) * (BN / TN);
    __shared__ float As[BK][BM];
    __shared__ float Bs[BK][BN];

    const int tid  = threadIdx.x;
    const int tcol = tid % (BN / TN);
    const int trow = tid / (BN / TN);

    const float* Ab = A + (size_t)blockIdx.y * BM * K;
    const float* Wb = W + (size_t)blockIdx.x * BN;

    float acc[TM][TN];
#pragma unroll
    for (int i = 0; i < TM; i++)
#pragma unroll
        for (int j = 0; j < TN; j++) acc[i][j] = 0.0f;

    for (int k0 = 0; k0 < K; k0 += BK) {
        // load A tile (BM x BK) as float4 along K, store transposed
#pragma unroll
        for (int l = tid; l < BM * BK / 4; l += NT) {
            int r = l / (BK / 4);
            int c = (l % (BK / 4)) * 4;
            float4 v = *(const float4*)(Ab + (size_t)r * K + k0 + c);
            As[c + 0][r] = v.x;
            As[c + 1][r] = v.y;
            As[c + 2][r] = v.z;
            As[c + 3][r] = v.w;
        }
        // load B tile (BK x BN), row-major, float4 coalesced
#pragma unroll
        for (int l = tid; l < BK * BN / 4; l += NT) {
            int r = l / (BN / 4);
            int c = (l % (BN / 4)) * 4;
            *(float4*)(&Bs[r][c]) = *(const float4*)(Wb + (size_t)(k0 + r) * N + c);
        }
        __syncthreads();

#pragma unroll
        for (int k = 0; k < BK; k++) {
            float regM[TM], regN[TN];
#pragma unroll
            for (int i = 0; i < TM; i += 4) {
                float4 v = *(const float4*)(&As[k][trow * TM + i]);
                regM[i] = v.x; regM[i + 1] = v.y; regM[i + 2] = v.z; regM[i + 3] = v.w;
            }
#pragma unroll
            for (int j = 0; j < TN; j += 4) {
                float4 v = *(const float4*)(&Bs[k][tcol * TN + j]);
                regN[j] = v.x; regN[j + 1] = v.y; regN[j + 2] = v.z; regN[j + 3] = v.w;
            }
#pragma unroll
            for (int i = 0; i < TM; i++)
#pragma unroll
                for (int j = 0; j < TN; j++)
                    acc[i][j] += regM[i] * regN[j];
        }
        __syncthreads();
    }

    // epilogue
#pragma unroll
    for (int i = 0; i < TM; i++) {
        size_t row = (size_t)blockIdx.y * BM + trow * TM + i;
#pragma unroll
        for (int j = 0; j < TN; j++) {
            size_t col = (size_t)blockIdx.x * BN + tcol * TN + j;
            float v = acc[i][j] + bias[col];
            if (EPI == EPI_BIAS_GELU)
                v = 0.5f * v * (1.0f + erff(v * 0.70710678118654752f));
            if (EPI == EPI_BIAS_RES)
                v += res[row * N + col];
            C[row * N + col] = v;
        }
    }
}

// ---------------------------------------------------------------------------
// Flash attention, fp32. Q/K/V layout: [b, n, h*DHEAD + d] (stride DMODEL).
// Grid: (NSEQ/32, NHEAD, BATCH). Block: 256 threads (16 tx x 16 ty).
// Per thread: 2 query rows x 4 key/output cols. Online softmax, m/l in regs
// (replicated across the 16 tx lanes via shfl reductions).
// Smem: Qs 32x65, KP 64x65 (K tile, then reused for P), Vs 64x65 => 40.6 KB.
// ---------------------------------------------------------------------------
#define BQ  32
#define BKV 64
#define SPAD 65

template<bool CAUSAL>
__global__ void __launch_bounds__(256)
flash_attn_k(const float* __restrict__ Q, const float* __restrict__ K,
             const float* __restrict__ V, float* __restrict__ O)
{
    __shared__ float Qs[BQ][SPAD];
    __shared__ float KP[BKV][SPAD];   // K tile, reused for P (32x64 fits)
    __shared__ float Vs[BKV][SPAD];

    const int tid = threadIdx.x;
    const int tx  = tid & 15;   // key / dhead group
    const int ty  = tid >> 4;   // query group
    const int qb  = blockIdx.x;
    const int h   = blockIdx.y;
    const int b   = blockIdx.z;

    const size_t base = (size_t)b * NSEQ * DMODEL + (size_t)h * DHEAD;

    // load Q tile (32 x 64)
#pragma unroll
    for (int l = tid; l < BQ * DHEAD / 4; l += 256) {
        int r  = l >> 4;
        int c4 = (l & 15) * 4;
        float4 v = *(const float4*)(Q + base + (size_t)(qb * BQ + r) * DMODEL + c4);
        Qs[r][c4] = v.x; Qs[r][c4 + 1] = v.y; Qs[r][c4 + 2] = v.z; Qs[r][c4 + 3] = v.w;
    }

    float m_i[2] = { -INFINITY, -INFINITY };
    float l_i[2] = { 0.0f, 0.0f };
    float acc[2][4] = {};

    const int nkt = CAUSAL ? ((qb * BQ + BQ - 1) / BKV + 1) : (NSEQ / BKV);

    for (int kt = 0; kt < nkt; kt++) {
        __syncthreads();   // Q load done / prev-iter P+V reads done
        // load K, V tiles (64 x 64 each)
#pragma unroll
        for (int l = tid; l < BKV * DHEAD / 4; l += 256) {
            int r  = l >> 4;
            int c4 = (l & 15) * 4;
            size_t go = base + (size_t)(kt * BKV + r) * DMODEL + c4;
            float4 kv = *(const float4*)(K + go);
            KP[r][c4] = kv.x; KP[r][c4 + 1] = kv.y; KP[r][c4 + 2] = kv.z; KP[r][c4 + 3] = kv.w;
            float4 vv = *(const float4*)(V + go);
            Vs[r][c4] = vv.x; Vs[r][c4 + 1] = vv.y; Vs[r][c4 + 2] = vv.z; Vs[r][c4 + 3] = vv.w;
        }
        __syncthreads();

        // S = Qs . Ks^T  (2 q-rows x 4 k-cols per thread)
        float s[2][4] = {};
#pragma unroll
        for (int d = 0; d < DHEAD; d++) {
            float a0 = Qs[ty * 2 + 0][d];
            float a1 = Qs[ty * 2 + 1][d];
#pragma unroll
            for (int j = 0; j < 4; j++) {
                float bb = KP[tx * 4 + j][d];
                s[0][j] += a0 * bb;
                s[1][j] += a1 * bb;
            }
        }

        // scale + causal mask
#pragma unroll
        for (int i = 0; i < 2; i++) {
            int qg = qb * BQ + ty * 2 + i;
#pragma unroll
            for (int j = 0; j < 4; j++) {
                s[i][j] *= 0.125f;   // 1/sqrt(64)
                if (CAUSAL && (kt * BKV + tx * 4 + j > qg))
                    s[i][j] = -INFINITY;
            }
        }

        // online softmax update (reductions over the 16 tx lanes)
        float mnew[2], alpha[2];
#pragma unroll
        for (int i = 0; i < 2; i++) {
            float t = fmaxf(fmaxf(s[i][0], s[i][1]), fmaxf(s[i][2], s[i][3]));
#pragma unroll
            for (int off = 1; off < 16; off <<= 1)
                t = fmaxf(t, __shfl_xor_sync(0xffffffffu, t, off));
            mnew[i]  = fmaxf(m_i[i], t);
            alpha[i] = __expf(m_i[i] - mnew[i]);
#pragma unroll
            for (int j = 0; j < 4; j++)
                s[i][j] = __expf(s[i][j] - mnew[i]);
            float rs = s[i][0] + s[i][1] + s[i][2] + s[i][3];
#pragma unroll
            for (int off = 1; off < 16; off <<= 1)
                rs += __shfl_xor_sync(0xffffffffu, rs, off);
            l_i[i] = l_i[i] * alpha[i] + rs;
            m_i[i] = mnew[i];
#pragma unroll
            for (int j = 0; j < 4; j++)
                acc[i][j] *= alpha[i];
        }

        __syncthreads();   // all S-compute reads of KP (as K) done
        // write P into KP (rows 0..31 = q, cols 0..63 = k)
#pragma unroll
        for (int i = 0; i < 2; i++)
#pragma unroll
            for (int j = 0; j < 4; j++)
                KP[ty * 2 + i][tx * 4 + j] = s[i][j];
        __syncthreads();

        // acc += P . V  (4 dhead cols per thread)
#pragma unroll
        for (int k = 0; k < BKV; k++) {
            float p0 = KP[ty * 2 + 0][k];
            float p1 = KP[ty * 2 + 1][k];
#pragma unroll
            for (int j = 0; j < 4; j++) {
                float vv = Vs[k][tx * 4 + j];
                acc[0][j] += p0 * vv;
                acc[1][j] += p1 * vv;
            }
        }
    }

    // write normalized output
#pragma unroll
    for (int i = 0; i < 2; i++) {
        int qg = qb * BQ + ty * 2 + i;
        float inv = 1.0f / l_i[i];
        float4 o;
        o.x = acc[i][0] * inv;
        o.y = acc[i][1] * inv;
        o.z = acc[i][2] * inv;
        o.w = acc[i][3] * inv;
        *(float4*)(O + base + (size_t)qg * DMODEL + tx * 4) = o;
    }
}

// ---------------------------------------------------------------------------
// LayerNorm over last dim (512). One block (128 threads) per token row.
// ---------------------------------------------------------------------------
__global__ void __launch_bounds__(128)
ln_k(const float* __restrict__ x, const float* __restrict__ gamma,
     const float* __restrict__ beta, float* __restrict__ out)
{
    __shared__ float red[8];
    const int row = blockIdx.x;
    const int t = threadIdx.x;
    const float* xr = x + (size_t)row * DMODEL;

    float4 v = *(const float4*)(xr + t * 4);
    float s = v.x + v.y + v.z + v.w;
    float q = v.x * v.x + v.y * v.y + v.z * v.z + v.w * v.w;
#pragma unroll
    for (int off = 16; off > 0; off >>= 1) {
        s += __shfl_xor_sync(0xffffffffu, s, off);
        q += __shfl_xor_sync(0xffffffffu, q, off);
    }
    int w = t >> 5;
    if ((t & 31) == 0) { red[w] = s; red[4 + w] = q; }
    __syncthreads();
    s = red[0] + red[1] + red[2] + red[3];
    q = red[4] + red[5] + red[6] + red[7];

    float mu  = s * (1.0f / DMODEL);
    float var = q * (1.0f / DMODEL) - mu * mu;
    float inv = rsqrtf(var + 1e-5f);

    float4 gg = *(const float4*)(gamma + t * 4);
    float4 bb = *(const float4*)(beta  + t * 4);
    float4 o;
    o.x = (v.x - mu) * inv * gg.x + bb.x;
    o.y = (v.y - mu) * inv * gg.y + bb.y;
    o.z = (v.z - mu) * inv * gg.z + bb.z;
    o.w = (v.w - mu) * inv * gg.w + bb.w;
    *(float4*)(out + (size_t)row * DMODEL + t * 4) = o;
}

// ---------------------------------------------------------------------------
extern "C" void kernel_launch(void* const* d_in, const int* in_sizes, int n_in,
                              void* d_out, int out_size)
{
    const float* x     = (const float*)d_in[0];
    const float* enc   = (const float*)d_in[1];
    const float* m_wq  = (const float*)d_in[2];
    const float* m_bq  = (const float*)d_in[3];
    const float* m_wk  = (const float*)d_in[4];
    const float* m_bk  = (const float*)d_in[5];
    const float* m_wv  = (const float*)d_in[6];
    const float* m_bv  = (const float*)d_in[7];
    const float* m_wo  = (const float*)d_in[8];
    const float* m_bo  = (const float*)d_in[9];
    const float* c_wq  = (const float*)d_in[10];
    const float* c_bq  = (const float*)d_in[11];
    const float* c_wk  = (const float*)d_in[12];
    const float* c_bk  = (const float*)d_in[13];
    const float* c_wv  = (const float*)d_in[14];
    const float* c_bv  = (const float*)d_in[15];
    const float* c_wo  = (const float*)d_in[16];
    const float* c_bo  = (const float*)d_in[17];
    const float* ln1_g = (const float*)d_in[18];
    const float* ln1_b = (const float*)d_in[19];
    const float* ln2_g = (const float*)d_in[20];
    const float* ln2_b = (const float*)d_in[21];
    const float* ln3_g = (const float*)d_in[22];
    const float* ln3_b = (const float*)d_in[23];
    const float* ff_w1 = (const float*)d_in[24];
    const float* ff_b1 = (const float*)d_in[25];
    const float* ff_w2 = (const float*)d_in[26];
    const float* ff_b2 = (const float*)d_in[27];

    float *q, *k, *v, *attn, *t0, *x1, *x2, *ff;
    cudaGetSymbolAddress((void**)&q,    g_q);
    cudaGetSymbolAddress((void**)&k,    g_k);
    cudaGetSymbolAddress((void**)&v,    g_v);
    cudaGetSymbolAddress((void**)&attn, g_attn);
    cudaGetSymbolAddress((void**)&t0,   g_t0);
    cudaGetSymbolAddress((void**)&x1,   g_x1);
    cudaGetSymbolAddress((void**)&x2,   g_x2);
    cudaGetSymbolAddress((void**)&ff,   g_ff);

    const dim3 gP(DMODEL / 64, TKN / 128);         // projection GEMMs
    const dim3 gF1(DFF / 128, TKN / 128);          // FF1
    const dim3 gA(NSEQ / BQ, NHEAD, BATCH);        // attention

    // ---- masked self-attention ----
    sgemm_k<128, 64, 16, 8, 4, EPI_BIAS><<<gP, 256>>>(x, m_wq, m_bq, nullptr, q, TKN, DMODEL, DMODEL);
    sgemm_k<128, 64, 16, 8, 4, EPI_BIAS><<<gP, 256>>>(x, m_wk, m_bk, nullptr, k, TKN, DMODEL, DMODEL);
    sgemm_k<128, 64, 16, 8, 4, EPI_BIAS><<<gP, 256>>>(x, m_wv, m_bv, nullptr, v, TKN, DMODEL, DMODEL);
    flash_attn_k<true><<<gA, 256>>>(q, k, v, attn);
    sgemm_k<128, 64, 16, 8, 4, EPI_BIAS_RES><<<gP, 256>>>(attn, m_wo, m_bo, x, t0, TKN, DMODEL, DMODEL);
    ln_k<<<TKN, 128>>>(t0, ln1_g, ln1_b, x1);

    // ---- cross-attention ----
    sgemm_k<128, 64, 16, 8, 4, EPI_BIAS><<<gP, 256>>>(x1,  c_wq, c_bq, nullptr, q, TKN, DMODEL, DMODEL);
    sgemm_k<128, 64, 16, 8, 4, EPI_BIAS><<<gP, 256>>>(enc, c_wk, c_bk, nullptr, k, TKN, DMODEL, DMODEL);
    sgemm_k<128, 64, 16, 8, 4, EPI_BIAS><<<gP, 256>>>(enc, c_wv, c_bv, nullptr, v, TKN, DMODEL, DMODEL);
    flash_attn_k<false><<<gA, 256>>>(q, k, v, attn);
    sgemm_k<128, 64, 16, 8, 4, EPI_BIAS_RES><<<gP, 256>>>(attn, c_wo, c_bo, x1, t0, TKN, DMODEL, DMODEL);
    ln_k<<<TKN, 128>>>(t0, ln2_g, ln2_b, x2);

    // ---- feed-forward ----
    sgemm_k<128, 128, 8, 8, 8, EPI_BIAS_GELU><<<gF1, 256>>>(x2, ff_w1, ff_b1, nullptr, ff, TKN, DFF, DMODEL);
    sgemm_k<128, 64, 16, 8, 4, EPI_BIAS_RES><<<gP, 256>>>(ff, ff_w2, ff_b2, x2, t0, TKN, DMODEL, DFF);
    ln_k<<<TKN, 128>>>(t0, ln3_g, ln3_b, (float*)d_out);
}

// round 8
// speedup vs baseline: 1.3303x; 1.3303x over previous
#include <cuda_runtime.h>
#include <math.h>

// ---------------------------------------------------------------------------
// Decoder layer: B=2, N=2048, D=512, H=8, Dh=64, FF=2048.  fp32 with packed
// f32x2 FFMA (sm_103a FFMA2) in all GEMM / attention inner loops.
// ---------------------------------------------------------------------------

#define NSEQ   2048
#define BATCH  2
#define DMODEL 512
#define NHEAD  8
#define DHEAD  64
#define DFF    2048
#define TKN    (BATCH * NSEQ)

typedef unsigned long long ull;

// ---------------- device scratch (no allocations allowed) ------------------
__device__ float g_q   [TKN * DMODEL];
__device__ float g_k   [TKN * DMODEL];
__device__ float g_v   [TKN * DMODEL];
__device__ float g_attn[TKN * DMODEL];
__device__ float g_t0  [TKN * DMODEL];
__device__ float g_x1  [TKN * DMODEL];
__device__ float g_x2  [TKN * DMODEL];
__device__ float g_ff  [TKN * DFF];

enum { EPI_BIAS = 0, EPI_BIAS_RES = 1, EPI_BIAS_GELU = 2 };

// ---------------- f32x2 helpers --------------------------------------------
__device__ __forceinline__ void ffma2(ull& d, ull a, ull b) {
    asm("fma.rn.f32x2 %0, %1, %2, %0;" : "+l"(d) : "l"(a), "l"(b));
}
__device__ __forceinline__ void fmul2(ull& d, ull a, ull b) {
    asm("mul.rn.f32x2 %0, %1, %2;" : "=l"(d) : "l"(a), "l"(b));
}
__device__ __forceinline__ ull dup2(float x) {
    ull r; asm("mov.b64 %0, {%1, %2};" : "=l"(r) : "f"(x), "f"(x)); return r;
}
__device__ __forceinline__ void unpack2(float& x, float& y, ull v) {
    asm("mov.b64 {%0, %1}, %2;" : "=f"(x), "=f"(y) : "l"(v));
}

// ---------------------------------------------------------------------------
// SGEMM with FFMA2: C[M,N] = A[M,K] @ W[K,N] + bias (+res / gelu).
// BM=BN=128, BK=16, 256 threads, 8x8 per thread.
// Thread (trow, tcol) owns rows trow*8..+7 (packed as 4 f32x2 pairs, A-tile
// stored K-transposed so M is contiguous) and SPLIT columns
// {tcol*4..+3, 64+tcol*4..+3} -> both Bs LDS.128 are bank-conflict-free
// (each 8-lane phase covers words 0..31 exactly once).
// ---------------------------------------------------------------------------
template<int EPI>
__global__ void __launch_bounds__(256)
sgemm2_k(const float* __restrict__ A, const float* __restrict__ W,
         const float* __restrict__ bias, const float* __restrict__ res,
         float* __restrict__ C, int N, int K)
{
    __shared__ float As[16][128];
    __shared__ float Bs[16][128];

    const int tid  = threadIdx.x;
    const int tcol = tid & 15;
    const int trow = tid >> 4;

    const float* Ab = A + (size_t)blockIdx.y * 128 * K;
    const float* Wb = W + (size_t)blockIdx.x * 128;

    ull acc2[4][8];
#pragma unroll
    for (int i = 0; i < 4; i++)
#pragma unroll
        for (int j = 0; j < 8; j++) acc2[i][j] = 0ull;

    for (int k0 = 0; k0 < K; k0 += 16) {
        // A tile 128x16, stored transposed As[k][m]
#pragma unroll
        for (int l = tid; l < 512; l += 256) {
            int r = l >> 2;
            int c = (l & 3) * 4;
            float4 v = *(const float4*)(Ab + (size_t)r * K + k0 + c);
            As[c + 0][r] = v.x; As[c + 1][r] = v.y;
            As[c + 2][r] = v.z; As[c + 3][r] = v.w;
        }
        // B tile 16x128 row-major
#pragma unroll
        for (int l = tid; l < 512; l += 256) {
            int r = l >> 5;
            int c = (l & 31) * 4;
            *(float4*)&Bs[r][c] = *(const float4*)(Wb + (size_t)(k0 + r) * N + c);
        }
        __syncthreads();

#pragma unroll
        for (int k = 0; k < 16; k++) {
            ulonglong2 a01 = *(const ulonglong2*)&As[k][trow * 8];
            ulonglong2 a23 = *(const ulonglong2*)&As[k][trow * 8 + 4];
            float4 b0 = *(const float4*)&Bs[k][tcol * 4];        // cols tcol*4..+3
            float4 b1 = *(const float4*)&Bs[k][tcol * 4 + 64];   // cols 64+tcol*4..+3
            const float bf[8] = { b0.x, b0.y, b0.z, b0.w, b1.x, b1.y, b1.z, b1.w };
#pragma unroll
            for (int j = 0; j < 8; j++) {
                ull bd = dup2(bf[j]);
                ffma2(acc2[0][j], a01.x, bd);
                ffma2(acc2[1][j], a01.y, bd);
                ffma2(acc2[2][j], a23.x, bd);
                ffma2(acc2[3][j], a23.y, bd);
            }
        }
        __syncthreads();
    }

    // epilogue: columns c0 = base + tcol*4 (j 0..3), c1 = c0 + 64 (j 4..7)
    const size_t c0 = (size_t)blockIdx.x * 128 + tcol * 4;
    const size_t c1 = c0 + 64;
    float4 bia0 = *(const float4*)(bias + c0);
    float4 bia1 = *(const float4*)(bias + c1);
    const float bv[8] = { bia0.x, bia0.y, bia0.z, bia0.w,
                          bia1.x, bia1.y, bia1.z, bia1.w };
#pragma unroll
    for (int mi = 0; mi < 4; mi++) {
        float lo[8], hi[8];
#pragma unroll
        for (int j = 0; j < 8; j++) unpack2(lo[j], hi[j], acc2[mi][j]);
#pragma unroll
        for (int h = 0; h < 2; h++) {
            const float* vv = h ? hi : lo;
            size_t row = (size_t)blockIdx.y * 128 + trow * 8 + 2 * mi + h;
            float o[8];
#pragma unroll
            for (int j = 0; j < 8; j++) {
                float v = vv[j] + bv[j];
                if (EPI == EPI_BIAS_GELU)
                    v = 0.5f * v * (1.0f + erff(v * 0.70710678118654752f));
                o[j] = v;
            }
            if (EPI == EPI_BIAS_RES) {
                float4 r0 = *(const float4*)(res + row * N + c0);
                float4 r1 = *(const float4*)(res + row * N + c1);
                o[0] += r0.x; o[1] += r0.y; o[2] += r0.z; o[3] += r0.w;
                o[4] += r1.x; o[5] += r1.y; o[6] += r1.z; o[7] += r1.w;
            }
            *(float4*)(C + row * N + c0) = make_float4(o[0], o[1], o[2], o[3]);
            *(float4*)(C + row * N + c1) = make_float4(o[4], o[5], o[6], o[7]);
        }
    }
}

// ---------------------------------------------------------------------------
// Flash attention, fp32 + FFMA2. BQ=64, BKV=64. Block 256 = 16 tx (k/dh
// groups) x 16 ty (q groups); per-thread 4q x 4k.
// K stored transposed+swizzled (conflict-free LDS.128 along k at each d);
// V swizzled along d; Q row-major (broadcast reads). P reuses K buffer.
// S packed over k-pairs, PV packed over d-pairs. Smem = 3 x 16KB = 48KB.
// ---------------------------------------------------------------------------
template<bool CAUSAL>
__global__ void __launch_bounds__(256)
flash2_k(const float* __restrict__ Q, const float* __restrict__ K,
         const float* __restrict__ V, float* __restrict__ O)
{
    __shared__ float Qs [64][64];   // [q][d]
    __shared__ float KtP[64][64];   // K: [d][swz(k)]  then P: [q][swz(k)]
    __shared__ float Vs [64][64];   // [k][swz(d)]

    const int tid = threadIdx.x;
    const int tx  = tid & 15;
    const int ty  = tid >> 4;
    const int qb  = blockIdx.x;
    const int h   = blockIdx.y;
    const int b   = blockIdx.z;

    const size_t base = (size_t)b * NSEQ * DMODEL + (size_t)h * DHEAD;

    // load Q tile (64 x 64), row-major
#pragma unroll
    for (int l = tid; l < 64 * 16; l += 256) {
        int r = l >> 4, t = l & 15;
        *(float4*)&Qs[r][t * 4] =
            *(const float4*)(Q + base + (size_t)(qb * 64 + r) * DMODEL + t * 4);
    }

    float m_i[4], l_i[4];
    ull o2[4][2];
#pragma unroll
    for (int i = 0; i < 4; i++) {
        m_i[i] = -INFINITY; l_i[i] = 0.0f; o2[i][0] = 0ull; o2[i][1] = 0ull;
    }

    const int nkt = CAUSAL ? (qb + 1) : (NSEQ / 64);

    for (int kt = 0; kt < nkt; kt++) {
        __syncthreads();   // Q fill done / prev-iter P+V reads done
        // fill K (transposed, swizzled) and V (swizzled)
#pragma unroll
        for (int l = tid; l < 64 * 16; l += 256) {
            int r = l >> 4, t = l & 15, c4 = t * 4;
            size_t go = base + (size_t)(kt * 64 + r) * DMODEL + c4;
            float4 kv = *(const float4*)(K + go);
            int r4 = r >> 2, rm = r & 3;
            KtP[c4 + 0][((r4 ^ ((c4 + 0) & 15)) << 2) + rm] = kv.x;
            KtP[c4 + 1][((r4 ^ ((c4 + 1) & 15)) << 2) + rm] = kv.y;
            KtP[c4 + 2][((r4 ^ ((c4 + 2) & 15)) << 2) + rm] = kv.z;
            KtP[c4 + 3][((r4 ^ ((c4 + 3) & 15)) << 2) + rm] = kv.w;
            float4 vv = *(const float4*)(V + go);
            *(float4*)&Vs[r][(t ^ (r & 15)) << 2] = vv;
        }
        __syncthreads();

        // ---- S = Q K^T, packed over k-pairs ----
        ull s2[4][2];
#pragma unroll
        for (int i = 0; i < 4; i++) { s2[i][0] = 0ull; s2[i][1] = 0ull; }

#pragma unroll 4
        for (int d0 = 0; d0 < 64; d0 += 4) {
            ulonglong2 kp[4];
#pragma unroll
            for (int dd = 0; dd < 4; dd++) {
                int d = d0 + dd;
                kp[dd] = *(const ulonglong2*)&KtP[d][(tx ^ (d & 15)) << 2];
            }
#pragma unroll
            for (int i = 0; i < 4; i++) {
                float4 qv = *(const float4*)&Qs[ty * 4 + i][d0];
                ull qd;
                qd = dup2(qv.x); ffma2(s2[i][0], kp[0].x, qd); ffma2(s2[i][1], kp[0].y, qd);
                qd = dup2(qv.y); ffma2(s2[i][0], kp[1].x, qd); ffma2(s2[i][1], kp[1].y, qd);
                qd = dup2(qv.z); ffma2(s2[i][0], kp[2].x, qd); ffma2(s2[i][1], kp[2].y, qd);
                qd = dup2(qv.w); ffma2(s2[i][0], kp[3].x, qd); ffma2(s2[i][1], kp[3].y, qd);
            }
        }

        // ---- softmax (unpacked) ----
        float s[4][4];
#pragma unroll
        for (int i = 0; i < 4; i++) {
            unpack2(s[i][0], s[i][1], s2[i][0]);
            unpack2(s[i][2], s[i][3], s2[i][1]);
        }
#pragma unroll
        for (int i = 0; i < 4; i++) {
            const int qg = qb * 64 + ty * 4 + i;
#pragma unroll
            for (int j = 0; j < 4; j++) {
                s[i][j] *= 0.125f;  // 1/sqrt(64)
                if (CAUSAL && (kt * 64 + tx * 4 + j > qg))
                    s[i][j] = -INFINITY;
            }
            float t = fmaxf(fmaxf(s[i][0], s[i][1]), fmaxf(s[i][2], s[i][3]));
#pragma unroll
            for (int off = 1; off < 16; off <<= 1)
                t = fmaxf(t, __shfl_xor_sync(0xffffffffu, t, off));
            float mnew  = fmaxf(m_i[i], t);
            float alpha = __expf(m_i[i] - mnew);
#pragma unroll
            for (int j = 0; j < 4; j++) s[i][j] = __expf(s[i][j] - mnew);
            float rs = s[i][0] + s[i][1] + s[i][2] + s[i][3];
#pragma unroll
            for (int off = 1; off < 16; off <<= 1)
                rs += __shfl_xor_sync(0xffffffffu, rs, off);
            l_i[i] = l_i[i] * alpha + rs;
            m_i[i] = mnew;
            ull ad = dup2(alpha);
            fmul2(o2[i][0], o2[i][0], ad);
            fmul2(o2[i][1], o2[i][1], ad);
        }

        __syncthreads();   // all K reads done before overwriting with P
        // write P into KtP: P[q][k] at q*64 + ((k>>2)^(q&15))*4 + (k&3)
#pragma unroll
        for (int i = 0; i < 4; i++) {
            int q = ty * 4 + i;
            *(float4*)&KtP[q][(tx ^ (q & 15)) << 2] =
                make_float4(s[i][0], s[i][1], s[i][2], s[i][3]);
        }
        __syncthreads();

        // ---- O += P V, packed over d-pairs ----
#pragma unroll 4
        for (int kk0 = 0; kk0 < 64; kk0 += 4) {
            ulonglong2 vp[4];
#pragma unroll
            for (int kk = 0; kk < 4; kk++) {
                int kg = kk0 + kk;
                vp[kk] = *(const ulonglong2*)&Vs[kg][(tx ^ (kg & 15)) << 2];
            }
#pragma unroll
            for (int i = 0; i < 4; i++) {
                int q = ty * 4 + i;
                float4 pv = *(const float4*)&KtP[q][(((kk0 >> 2) ^ (q & 15))) << 2];
                ull pd;
                pd = dup2(pv.x); ffma2(o2[i][0], vp[0].x, pd); ffma2(o2[i][1], vp[0].y, pd);
                pd = dup2(pv.y); ffma2(o2[i][0], vp[1].x, pd); ffma2(o2[i][1], vp[1].y, pd);
                pd = dup2(pv.z); ffma2(o2[i][0], vp[2].x, pd); ffma2(o2[i][1], vp[2].y, pd);
                pd = dup2(pv.w); ffma2(o2[i][0], vp[3].x, pd); ffma2(o2[i][1], vp[3].y, pd);
            }
        }
    }

    // write normalized output
#pragma unroll
    for (int i = 0; i < 4; i++) {
        float inv = 1.0f / l_i[i];
        float a, bb, c, d;
        unpack2(a, bb, o2[i][0]);
        unpack2(c, d,  o2[i][1]);
        int q = qb * 64 + ty * 4 + i;
        *(float4*)(O + base + (size_t)q * DMODEL + tx * 4) =
            make_float4(a * inv, bb * inv, c * inv, d * inv);
    }
}

// ---------------------------------------------------------------------------
// LayerNorm over last dim (512). One block (128 threads) per token row.
// ---------------------------------------------------------------------------
__global__ void __launch_bounds__(128)
ln_k(const float* __restrict__ x, const float* __restrict__ gamma,
     const float* __restrict__ beta, float* __restrict__ out)
{
    __shared__ float red[8];
    const int row = blockIdx.x;
    const int t = threadIdx.x;
    const float* xr = x + (size_t)row * DMODEL;

    float4 v = *(const float4*)(xr + t * 4);
    float s = v.x + v.y + v.z + v.w;
    float q = v.x * v.x + v.y * v.y + v.z * v.z + v.w * v.w;
#pragma unroll
    for (int off = 16; off > 0; off >>= 1) {
        s += __shfl_xor_sync(0xffffffffu, s, off);
        q += __shfl_xor_sync(0xffffffffu, q, off);
    }
    int w = t >> 5;
    if ((t & 31) == 0) { red[w] = s; red[4 + w] = q; }
    __syncthreads();
    s = red[0] + red[1] + red[2] + red[3];
    q = red[4] + red[5] + red[6] + red[7];

    float mu  = s * (1.0f / DMODEL);
    float var = q * (1.0f / DMODEL) - mu * mu;
    float inv = rsqrtf(var + 1e-5f);

    float4 gg = *(const float4*)(gamma + t * 4);
    float4 bb = *(const float4*)(beta  + t * 4);
    float4 o;
    o.x = (v.x - mu) * inv * gg.x + bb.x;
    o.y = (v.y - mu) * inv * gg.y + bb.y;
    o.z = (v.z - mu) * inv * gg.z + bb.z;
    o.w = (v.w - mu) * inv * gg.w + bb.w;
    *(float4*)(out + (size_t)row * DMODEL + t * 4) = o;
}

// ---------------------------------------------------------------------------
extern "C" void kernel_launch(void* const* d_in, const int* in_sizes, int n_in,
                              void* d_out, int out_size)
{
    const float* x     = (const float*)d_in[0];
    const float* enc   = (const float*)d_in[1];
    const float* m_wq  = (const float*)d_in[2];
    const float* m_bq  = (const float*)d_in[3];
    const float* m_wk  = (const float*)d_in[4];
    const float* m_bk  = (const float*)d_in[5];
    const float* m_wv  = (const float*)d_in[6];
    const float* m_bv  = (const float*)d_in[7];
    const float* m_wo  = (const float*)d_in[8];
    const float* m_bo  = (const float*)d_in[9];
    const float* c_wq  = (const float*)d_in[10];
    const float* c_bq  = (const float*)d_in[11];
    const float* c_wk  = (const float*)d_in[12];
    const float* c_bk  = (const float*)d_in[13];
    const float* c_wv  = (const float*)d_in[14];
    const float* c_bv  = (const float*)d_in[15];
    const float* c_wo  = (const float*)d_in[16];
    const float* c_bo  = (const float*)d_in[17];
    const float* ln1_g = (const float*)d_in[18];
    const float* ln1_b = (const float*)d_in[19];
    const float* ln2_g = (const float*)d_in[20];
    const float* ln2_b = (const float*)d_in[21];
    const float* ln3_g = (const float*)d_in[22];
    const float* ln3_b = (const float*)d_in[23];
    const float* ff_w1 = (const float*)d_in[24];
    const float* ff_b1 = (const float*)d_in[25];
    const float* ff_w2 = (const float*)d_in[26];
    const float* ff_b2 = (const float*)d_in[27];

    float *q, *k, *v, *attn, *t0, *x1, *x2, *ff;
    cudaGetSymbolAddress((void**)&q,    g_q);
    cudaGetSymbolAddress((void**)&k,    g_k);
    cudaGetSymbolAddress((void**)&v,    g_v);
    cudaGetSymbolAddress((void**)&attn, g_attn);
    cudaGetSymbolAddress((void**)&t0,   g_t0);
    cudaGetSymbolAddress((void**)&x1,   g_x1);
    cudaGetSymbolAddress((void**)&x2,   g_x2);
    cudaGetSymbolAddress((void**)&ff,   g_ff);

    const dim3 gP(DMODEL / 128, TKN / 128);   // 512-col GEMMs: 4 x 32
    const dim3 gF1(DFF / 128, TKN / 128);     // FF1: 16 x 32
    const dim3 gA(NSEQ / 64, NHEAD, BATCH);   // attention: 32 x 8 x 2

    // ---- masked self-attention ----
    sgemm2_k<EPI_BIAS><<<gP, 256>>>(x, m_wq, m_bq, nullptr, q, DMODEL, DMODEL);
    sgemm2_k<EPI_BIAS><<<gP, 256>>>(x, m_wk, m_bk, nullptr, k, DMODEL, DMODEL);
    sgemm2_k<EPI_BIAS><<<gP, 256>>>(x, m_wv, m_bv, nullptr, v, DMODEL, DMODEL);
    flash2_k<true><<<gA, 256>>>(q, k, v, attn);
    sgemm2_k<EPI_BIAS_RES><<<gP, 256>>>(attn, m_wo, m_bo, x, t0, DMODEL, DMODEL);
    ln_k<<<TKN, 128>>>(t0, ln1_g, ln1_b, x1);

    // ---- cross-attention ----
    sgemm2_k<EPI_BIAS><<<gP, 256>>>(x1,  c_wq, c_bq, nullptr, q, DMODEL, DMODEL);
    sgemm2_k<EPI_BIAS><<<gP, 256>>>(enc, c_wk, c_bk, nullptr, k, DMODEL, DMODEL);
    sgemm2_k<EPI_BIAS><<<gP, 256>>>(enc, c_wv, c_bv, nullptr, v, DMODEL, DMODEL);
    flash2_k<false><<<gA, 256>>>(q, k, v, attn);
    sgemm2_k<EPI_BIAS_RES><<<gP, 256>>>(attn, c_wo, c_bo, x1, t0, DMODEL, DMODEL);
    ln_k<<<TKN, 128>>>(t0, ln2_g, ln2_b, x2);

    // ---- feed-forward ----
    sgemm2_k<EPI_BIAS_GELU><<<gF1, 256>>>(x2, ff_w1, ff_b1, nullptr, ff, DFF, DMODEL);
    sgemm2_k<EPI_BIAS_RES><<<gP, 256>>>(ff, ff_w2, ff_b2, x2, t0, DMODEL, DFF);
    ln_k<<<TKN, 128>>>(t0, ln3_g, ln3_b, (float*)d_out);
}

// round 10
// speedup vs baseline: 1.8126x; 1.3626x over previous
#include <cuda_runtime.h>
#include <cuda_bf16.h>
#include <math.h>
#include <stdint.h>

// ---------------------------------------------------------------------------
// Decoder layer: B=2, N=2048, D=512, H=8, Dh=64, FF=2048.
// Linear GEMMs on HMMA (mma.sync bf16, 3-term split = fp32-accurate),
// attention on the proven fp32 FFMA2 flash kernel.
// NOTE: harness ptxas targets sm_103 (no 'a') -> tcgen05 unavailable;
// mma.sync/ldmatrix are baseline PTX ISA and compile fine.
// ---------------------------------------------------------------------------

#define NSEQ   2048
#define BATCH  2
#define DMODEL 512
#define NHEAD  8
#define DHEAD  64
#define DFF    2048
#define TKN    (BATCH * NSEQ)

typedef unsigned long long ull;

// ---------------- device scratch (no allocations allowed) ------------------
__device__ float g_q   [TKN * DMODEL];
__device__ float g_k   [TKN * DMODEL];
__device__ float g_v   [TKN * DMODEL];
__device__ float g_attn[TKN * DMODEL];
__device__ float g_t0  [TKN * DMODEL];
__device__ float g_x1  [TKN * DMODEL];
__device__ float g_x2  [TKN * DMODEL];
__device__ float g_ff  [TKN * DFF];

// bf16 split buffers
__device__ __nv_bfloat16 g_whi[4194304];      // transposed weights, hi
__device__ __nv_bfloat16 g_wlo[4194304];      // transposed weights, lo
__device__ __nv_bfloat16 g_ahi[TKN * DFF];    // activation hi
__device__ __nv_bfloat16 g_alo[TKN * DFF];    // activation lo
__device__ __nv_bfloat16 g_ehi[TKN * DMODEL]; // encoder hi
__device__ __nv_bfloat16 g_elo[TKN * DMODEL]; // encoder lo

#define OFF_MWQ 0
#define OFF_MWK 262144
#define OFF_MWV 524288
#define OFF_MWO 786432
#define OFF_CWQ 1048576
#define OFF_CWK 1310720
#define OFF_CWV 1572864
#define OFF_CWO 1835008
#define OFF_FF1 2097152
#define OFF_FF2 3145728

enum { EPI_BIAS = 0, EPI_BIAS_RES = 1, EPI_BIAS_GELU = 2 };

// ---------------- PTX helpers ----------------------------------------------
__device__ __forceinline__ uint32_t smem_u32(const void* p) {
    uint32_t a;
    asm("{ .reg .u64 t; cvta.to.shared.u64 t, %1; cvt.u32.u64 %0, t; }"
        : "=r"(a) : "l"(p));
    return a;
}
__device__ __forceinline__ void ldm_x4(uint32_t* r, uint32_t addr) {
    asm volatile("ldmatrix.sync.aligned.m8n8.x4.shared.b16 {%0,%1,%2,%3}, [%4];"
                 : "=r"(r[0]), "=r"(r[1]), "=r"(r[2]), "=r"(r[3]) : "r"(addr));
}
__device__ __forceinline__ void mma16816(float* c, const uint32_t* a,
                                         uint32_t b0, uint32_t b1) {
    asm volatile(
        "mma.sync.aligned.m16n8k16.row.col.f32.bf16.bf16.f32 "
        "{%0,%1,%2,%3}, {%4,%5,%6,%7}, {%8,%9}, {%0,%1,%2,%3};"
        : "+f"(c[0]), "+f"(c[1]), "+f"(c[2]), "+f"(c[3])
        : "r"(a[0]), "r"(a[1]), "r"(a[2]), "r"(a[3]), "r"(b0), "r"(b1));
}

// ---------------- f32x2 helpers (attention) ---------------------------------
__device__ __forceinline__ void ffma2(ull& d, ull a, ull b) {
    asm("fma.rn.f32x2 %0, %1, %2, %0;" : "+l"(d) : "l"(a), "l"(b));
}
__device__ __forceinline__ void fmul2(ull& d, ull a, ull b) {
    asm("mul.rn.f32x2 %0, %1, %2;" : "=l"(d) : "l"(a), "l"(b));
}
__device__ __forceinline__ ull dup2(float x) {
    ull r; asm("mov.b64 %0, {%1, %2};" : "=l"(r) : "f"(x), "f"(x)); return r;
}
__device__ __forceinline__ void unpack2(float& x, float& y, ull v) {
    asm("mov.b64 {%0, %1}, %2;" : "=f"(x), "=f"(y) : "l"(v));
}

// ---------------------------------------------------------------------------
// Conversion kernels: fp32 -> bf16 hi + bf16 lo (lo = round(x - hi))
// ---------------------------------------------------------------------------
__global__ void __launch_bounds__(256)
cvt_act_k(const float* __restrict__ x, __nv_bfloat16* __restrict__ hi,
          __nv_bfloat16* __restrict__ lo, int n4)
{
    int i = blockIdx.x * 256 + threadIdx.x;
    if (i >= n4) return;
    float4 v = ((const float4*)x)[i];
    float f[4] = { v.x, v.y, v.z, v.w };
    ushort4 hv, lv;
    unsigned short* hp = &hv.x;
    unsigned short* lp = &lv.x;
#pragma unroll
    for (int t = 0; t < 4; t++) {
        __nv_bfloat16 h = __float2bfloat16(f[t]);
        __nv_bfloat16 l = __float2bfloat16(f[t] - __bfloat162float(h));
        hp[t] = __bfloat16_as_ushort(h);
        lp[t] = __bfloat16_as_ushort(l);
    }
    ((ushort4*)hi)[i] = hv;
    ((ushort4*)lo)[i] = lv;
}

// W[K,N] fp32 -> Wt_hi/lo[N,K] bf16 (transpose + split), 32x32 smem tiles
__global__ void __launch_bounds__(256)
cvt_wt_k(const float* __restrict__ W, __nv_bfloat16* __restrict__ hi,
         __nv_bfloat16* __restrict__ lo, int K, int N)
{
    __shared__ float t[32][33];
    const int n0 = blockIdx.x * 32, k0 = blockIdx.y * 32;
    const int tx = threadIdx.x, ty = threadIdx.y;
#pragma unroll
    for (int i = 0; i < 32; i += 8)
        t[ty + i][tx] = W[(size_t)(k0 + ty + i) * N + n0 + tx];
    __syncthreads();
#pragma unroll
    for (int i = 0; i < 32; i += 8) {
        float v = t[tx][ty + i];                 // = W[k0+tx][n0+ty+i]
        __nv_bfloat16 h = __float2bfloat16(v);
        __nv_bfloat16 l = __float2bfloat16(v - __bfloat162float(h));
        size_t o = (size_t)(n0 + ty + i) * K + k0 + tx;
        hi[o] = h;
        lo[o] = l;
    }
}

// ---------------------------------------------------------------------------
// HMMA GEMM: C[M,N] = A[M,K] @ Wt^T + bias (+res / gelu)
//   A: bf16 hi/lo [M,K] row-major; Wt: bf16 hi/lo [N,K] row-major (= .col B).
//   3-term split: D += Ah*Bh + Ah*Bl + Al*Bh  (fp32 accumulate).
// Block 128x128, 256 thr = 8 warps; warp (w&1)->m-half 64, (w>>1)->n-quarter 32.
// BK=64 single stage; smem 64KB = 4 x [128][64] bf16 tiles, XOR-swizzled
// (16B unit c stored at c^(row&7)) -> conflict-free ldmatrix + stores.
// ---------------------------------------------------------------------------
template<int EPI>
__global__ void __launch_bounds__(256)
gemm_mma_k(const __nv_bfloat16* __restrict__ a_hi, const __nv_bfloat16* __restrict__ a_lo,
           const __nv_bfloat16* __restrict__ b_hi, const __nv_bfloat16* __restrict__ b_lo,
           const float* __restrict__ bias, const float* __restrict__ res,
           float* __restrict__ C, int N, int K)
{
    extern __shared__ __align__(128) char dsm[];

    const int tid  = threadIdx.x;
    const int wid  = tid >> 5;
    const int lane = tid & 31;
    const int m0 = blockIdx.y * 128;
    const int n0 = blockIdx.x * 128;
    const int wm = (wid & 1) * 64;    // warp m-offset in tile
    const int wn = (wid >> 1) * 32;   // warp n-offset in tile

    const uint32_t sb  = smem_u32(dsm);
    const uint32_t sAh = sb;
    const uint32_t sAl = sb + 16384u;
    const uint32_t sBh = sb + 32768u;
    const uint32_t sBl = sb + 49152u;

    float acc[4][4][4];
#pragma unroll
    for (int mi = 0; mi < 4; mi++)
#pragma unroll
        for (int nj = 0; nj < 4; nj++)
#pragma unroll
            for (int r = 0; r < 4; r++) acc[mi][nj][r] = 0.0f;

    const int nch = K >> 6;
    for (int ch = 0; ch < nch; ch++) {
        if (ch > 0) __syncthreads();       // all warps done reading prev tiles
        const int k0 = ch * 64;
#pragma unroll
        for (int i = 0; i < 4; i++) {
            int l = tid + i * 256;          // 0..1023
            int r = l >> 3;                 // row 0..127
            int c = l & 7;                  // 16B unit 0..7
            uint32_t soff = (uint32_t)(r * 128 + ((c ^ (r & 7)) << 4));
            size_t goA = (size_t)(m0 + r) * K + k0 + c * 8;
            size_t goB = (size_t)(n0 + r) * K + k0 + c * 8;
            *(uint4*)(dsm + soff)           = *(const uint4*)(a_hi + goA);
            *(uint4*)(dsm + 16384 + soff)   = *(const uint4*)(a_lo + goA);
            *(uint4*)(dsm + 32768 + soff)   = *(const uint4*)(b_hi + goB);
            *(uint4*)(dsm + 49152 + soff)   = *(const uint4*)(b_lo + goB);
        }
        __syncthreads();

#pragma unroll
        for (int ks = 0; ks < 4; ks++) {
            // B fragments: 2 x ldmatrix.x4 per matrix (hi, lo), covering n 0..31
            // lanes: g0 rows n+0..7 @ku, g1 rows n+0..7 @ku+1, g2 rows +8 @ku, g3 rows +8 @ku+1
            uint32_t Bh[2][4], Bl[2][4];
#pragma unroll
            for (int np = 0; np < 2; np++) {
                int brow = wn + np * 16 + (lane & 7) + ((lane >> 4) & 1) * 8;
                int bcu  = ks * 2 + ((lane >> 3) & 1);
                uint32_t ba = (uint32_t)(brow * 128 + ((bcu ^ (brow & 7)) << 4));
                ldm_x4(Bh[np], sBh + ba);
                ldm_x4(Bl[np], sBl + ba);
            }
#pragma unroll
            for (int mi = 0; mi < 4; mi++) {
                // A fragment: lanes 0-15 rows m+0..15 @ku, lanes 16-31 same rows @ku+1
                int arow = wm + mi * 16 + (lane & 15);
                int acu  = ks * 2 + (lane >> 4);
                uint32_t aa = (uint32_t)(arow * 128 + ((acu ^ (arow & 7)) << 4));
                uint32_t Ah[4], Al[4];
                ldm_x4(Ah, sAh + aa);
                ldm_x4(Al, sAl + aa);
#pragma unroll
                for (int nj = 0; nj < 4; nj++) {
                    const int np = nj >> 1, s = (nj & 1) * 2;
                    mma16816(acc[mi][nj], Ah, Bh[np][s], Bh[np][s + 1]);
                    mma16816(acc[mi][nj], Ah, Bl[np][s], Bl[np][s + 1]);
                    mma16816(acc[mi][nj], Al, Bh[np][s], Bh[np][s + 1]);
                }
            }
        }
    }

    // ---- epilogue: acc regs c0,c1 -> (row, col..col+1); c2,c3 -> (row+8, ..) ----
#pragma unroll
    for (int mi = 0; mi < 4; mi++) {
#pragma unroll
        for (int nj = 0; nj < 4; nj++) {
            size_t row = (size_t)m0 + wm + mi * 16 + (lane >> 2);
            size_t col = (size_t)n0 + wn + nj * 8 + (lane & 3) * 2;
            float b0 = bias[col], b1 = bias[col + 1];
#pragma unroll
            for (int h = 0; h < 2; h++) {
                size_t rw = row + h * 8;
                float o0 = acc[mi][nj][h * 2 + 0] + b0;
                float o1 = acc[mi][nj][h * 2 + 1] + b1;
                if (EPI == EPI_BIAS_GELU) {
                    o0 = 0.5f * o0 * (1.0f + erff(o0 * 0.70710678118654752f));
                    o1 = 0.5f * o1 * (1.0f + erff(o1 * 0.70710678118654752f));
                }
                if (EPI == EPI_BIAS_RES) {
                    float2 rv = *(const float2*)(res + rw * N + col);
                    o0 += rv.x; o1 += rv.y;
                }
                *(float2*)(C + rw * N + col) = make_float2(o0, o1);
            }
        }
    }
}

// ---------------------------------------------------------------------------
// Flash attention, fp32 + FFMA2 (unchanged from R8 passing kernel).
// ---------------------------------------------------------------------------
template<bool CAUSAL>
__global__ void __launch_bounds__(256)
flash2_k(const float* __restrict__ Q, const float* __restrict__ K,
         const float* __restrict__ V, float* __restrict__ O)
{
    __shared__ float Qs [64][64];   // [q][d]
    __shared__ float KtP[64][64];   // K: [d][swz(k)]  then P: [q][swz(k)]
    __shared__ float Vs [64][64];   // [k][swz(d)]

    const int tid = threadIdx.x;
    const int tx  = tid & 15;
    const int ty  = tid >> 4;
    const int qb  = blockIdx.x;
    const int h   = blockIdx.y;
    const int b   = blockIdx.z;

    const size_t base = (size_t)b * NSEQ * DMODEL + (size_t)h * DHEAD;

#pragma unroll
    for (int l = tid; l < 64 * 16; l += 256) {
        int r = l >> 4, t = l & 15;
        *(float4*)&Qs[r][t * 4] =
            *(const float4*)(Q + base + (size_t)(qb * 64 + r) * DMODEL + t * 4);
    }

    float m_i[4], l_i[4];
    ull o2[4][2];
#pragma unroll
    for (int i = 0; i < 4; i++) {
        m_i[i] = -INFINITY; l_i[i] = 0.0f; o2[i][0] = 0ull; o2[i][1] = 0ull;
    }

    const int nkt = CAUSAL ? (qb + 1) : (NSEQ / 64);

    for (int kt = 0; kt < nkt; kt++) {
        __syncthreads();
#pragma unroll
        for (int l = tid; l < 64 * 16; l += 256) {
            int r = l >> 4, t = l & 15, c4 = t * 4;
            size_t go = base + (size_t)(kt * 64 + r) * DMODEL + c4;
            float4 kv = *(const float4*)(K + go);
            int r4 = r >> 2, rm = r & 3;
            KtP[c4 + 0][((r4 ^ ((c4 + 0) & 15)) << 2) + rm] = kv.x;
            KtP[c4 + 1][((r4 ^ ((c4 + 1) & 15)) << 2) + rm] = kv.y;
            KtP[c4 + 2][((r4 ^ ((c4 + 2) & 15)) << 2) + rm] = kv.z;
            KtP[c4 + 3][((r4 ^ ((c4 + 3) & 15)) << 2) + rm] = kv.w;
            float4 vv = *(const float4*)(V + go);
            *(float4*)&Vs[r][(t ^ (r & 15)) << 2] = vv;
        }
        __syncthreads();

        ull s2[4][2];
#pragma unroll
        for (int i = 0; i < 4; i++) { s2[i][0] = 0ull; s2[i][1] = 0ull; }

#pragma unroll 4
        for (int d0 = 0; d0 < 64; d0 += 4) {
            ulonglong2 kp[4];
#pragma unroll
            for (int dd = 0; dd < 4; dd++) {
                int d = d0 + dd;
                kp[dd] = *(const ulonglong2*)&KtP[d][(tx ^ (d & 15)) << 2];
            }
#pragma unroll
            for (int i = 0; i < 4; i++) {
                float4 qv = *(const float4*)&Qs[ty * 4 + i][d0];
                ull qd;
                qd = dup2(qv.x); ffma2(s2[i][0], kp[0].x, qd); ffma2(s2[i][1], kp[0].y, qd);
                qd = dup2(qv.y); ffma2(s2[i][0], kp[1].x, qd); ffma2(s2[i][1], kp[1].y, qd);
                qd = dup2(qv.z); ffma2(s2[i][0], kp[2].x, qd); ffma2(s2[i][1], kp[2].y, qd);
                qd = dup2(qv.w); ffma2(s2[i][0], kp[3].x, qd); ffma2(s2[i][1], kp[3].y, qd);
            }
        }

        float s[4][4];
#pragma unroll
        for (int i = 0; i < 4; i++) {
            unpack2(s[i][0], s[i][1], s2[i][0]);
            unpack2(s[i][2], s[i][3], s2[i][1]);
        }
#pragma unroll
        for (int i = 0; i < 4; i++) {
            const int qg = qb * 64 + ty * 4 + i;
#pragma unroll
            for (int j = 0; j < 4; j++) {
                s[i][j] *= 0.125f;
                if (CAUSAL && (kt * 64 + tx * 4 + j > qg))
                    s[i][j] = -INFINITY;
            }
            float t = fmaxf(fmaxf(s[i][0], s[i][1]), fmaxf(s[i][2], s[i][3]));
#pragma unroll
            for (int off = 1; off < 16; off <<= 1)
                t = fmaxf(t, __shfl_xor_sync(0xffffffffu, t, off));
            float mnew  = fmaxf(m_i[i], t);
            float alpha = __expf(m_i[i] - mnew);
#pragma unroll
            for (int j = 0; j < 4; j++) s[i][j] = __expf(s[i][j] - mnew);
            float rs = s[i][0] + s[i][1] + s[i][2] + s[i][3];
#pragma unroll
            for (int off = 1; off < 16; off <<= 1)
                rs += __shfl_xor_sync(0xffffffffu, rs, off);
            l_i[i] = l_i[i] * alpha + rs;
            m_i[i] = mnew;
            ull ad = dup2(alpha);
            fmul2(o2[i][0], o2[i][0], ad);
            fmul2(o2[i][1], o2[i][1], ad);
        }

        __syncthreads();
#pragma unroll
        for (int i = 0; i < 4; i++) {
            int q = ty * 4 + i;
            *(float4*)&KtP[q][(tx ^ (q & 15)) << 2] =
                make_float4(s[i][0], s[i][1], s[i][2], s[i][3]);
        }
        __syncthreads();

#pragma unroll 4
        for (int kk0 = 0; kk0 < 64; kk0 += 4) {
            ulonglong2 vp[4];
#pragma unroll
            for (int kk = 0; kk < 4; kk++) {
                int kg = kk0 + kk;
                vp[kk] = *(const ulonglong2*)&Vs[kg][(tx ^ (kg & 15)) << 2];
            }
#pragma unroll
            for (int i = 0; i < 4; i++) {
                int q = ty * 4 + i;
                float4 pv = *(const float4*)&KtP[q][(((kk0 >> 2) ^ (q & 15))) << 2];
                ull pd;
                pd = dup2(pv.x); ffma2(o2[i][0], vp[0].x, pd); ffma2(o2[i][1], vp[0].y, pd);
                pd = dup2(pv.y); ffma2(o2[i][0], vp[1].x, pd); ffma2(o2[i][1], vp[1].y, pd);
                pd = dup2(pv.z); ffma2(o2[i][0], vp[2].x, pd); ffma2(o2[i][1], vp[2].y, pd);
                pd = dup2(pv.w); ffma2(o2[i][0], vp[3].x, pd); ffma2(o2[i][1], vp[3].y, pd);
            }
        }
    }

#pragma unroll
    for (int i = 0; i < 4; i++) {
        float inv = 1.0f / l_i[i];
        float a, bb, c, d;
        unpack2(a, bb, o2[i][0]);
        unpack2(c, d,  o2[i][1]);
        int q = qb * 64 + ty * 4 + i;
        *(float4*)(O + base + (size_t)q * DMODEL + tx * 4) =
            make_float4(a * inv, bb * inv, c * inv, d * inv);
    }
}

// ---------------------------------------------------------------------------
// LayerNorm over last dim (512). One block (128 threads) per token row.
// ---------------------------------------------------------------------------
__global__ void __launch_bounds__(128)
ln_k(const float* __restrict__ x, const float* __restrict__ gamma,
     const float* __restrict__ beta, float* __restrict__ out)
{
    __shared__ float red[8];
    const int row = blockIdx.x;
    const int t = threadIdx.x;
    const float* xr = x + (size_t)row * DMODEL;

    float4 v = *(const float4*)(xr + t * 4);
    float s = v.x + v.y + v.z + v.w;
    float q = v.x * v.x + v.y * v.y + v.z * v.z + v.w * v.w;
#pragma unroll
    for (int off = 16; off > 0; off >>= 1) {
        s += __shfl_xor_sync(0xffffffffu, s, off);
        q += __shfl_xor_sync(0xffffffffu, q, off);
    }
    int w = t >> 5;
    if ((t & 31) == 0) { red[w] = s; red[4 + w] = q; }
    __syncthreads();
    s = red[0] + red[1] + red[2] + red[3];
    q = red[4] + red[5] + red[6] + red[7];

    float mu  = s * (1.0f / DMODEL);
    float var = q * (1.0f / DMODEL) - mu * mu;
    float inv = rsqrtf(var + 1e-5f);

    float4 gg = *(const float4*)(gamma + t * 4);
    float4 bb = *(const float4*)(beta  + t * 4);
    float4 o;
    o.x = (v.x - mu) * inv * gg.x + bb.x;
    o.y = (v.y - mu) * inv * gg.y + bb.y;
    o.z = (v.z - mu) * inv * gg.z + bb.z;
    o.w = (v.w - mu) * inv * gg.w + bb.w;
    *(float4*)(out + (size_t)row * DMODEL + t * 4) = o;
}

// ---------------------------------------------------------------------------
extern "C" void kernel_launch(void* const* d_in, const int* in_sizes, int n_in,
                              void* d_out, int out_size)
{
    const float* x     = (const float*)d_in[0];
    const float* enc   = (const float*)d_in[1];
    const float* m_wq  = (const float*)d_in[2];
    const float* m_bq  = (const float*)d_in[3];
    const float* m_wk  = (const float*)d_in[4];
    const float* m_bk  = (const float*)d_in[5];
    const float* m_wv  = (const float*)d_in[6];
    const float* m_bv  = (const float*)d_in[7];
    const float* m_wo  = (const float*)d_in[8];
    const float* m_bo  = (const float*)d_in[9];
    const float* c_wq  = (const float*)d_in[10];
    const float* c_bq  = (const float*)d_in[11];
    const float* c_wk  = (const float*)d_in[12];
    const float* c_bk  = (const float*)d_in[13];
    const float* c_wv  = (const float*)d_in[14];
    const float* c_bv  = (const float*)d_in[15];
    const float* c_wo  = (const float*)d_in[16];
    const float* c_bo  = (const float*)d_in[17];
    const float* ln1_g = (const float*)d_in[18];
    const float* ln1_b = (const float*)d_in[19];
    const float* ln2_g = (const float*)d_in[20];
    const float* ln2_b = (const float*)d_in[21];
    const float* ln3_g = (const float*)d_in[22];
    const float* ln3_b = (const float*)d_in[23];
    const float* ff_w1 = (const float*)d_in[24];
    const float* ff_b1 = (const float*)d_in[25];
    const float* ff_w2 = (const float*)d_in[26];
    const float* ff_b2 = (const float*)d_in[27];

    float *q, *k, *v, *attn, *t0, *x1, *x2, *ff;
    __nv_bfloat16 *whi, *wlo, *ahi, *alo, *ehi, *elo;
    cudaGetSymbolAddress((void**)&q,    g_q);
    cudaGetSymbolAddress((void**)&k,    g_k);
    cudaGetSymbolAddress((void**)&v,    g_v);
    cudaGetSymbolAddress((void**)&attn, g_attn);
    cudaGetSymbolAddress((void**)&t0,   g_t0);
    cudaGetSymbolAddress((void**)&x1,   g_x1);
    cudaGetSymbolAddress((void**)&x2,   g_x2);
    cudaGetSymbolAddress((void**)&ff,   g_ff);
    cudaGetSymbolAddress((void**)&whi,  g_whi);
    cudaGetSymbolAddress((void**)&wlo,  g_wlo);
    cudaGetSymbolAddress((void**)&ahi,  g_ahi);
    cudaGetSymbolAddress((void**)&alo,  g_alo);
    cudaGetSymbolAddress((void**)&ehi,  g_ehi);
    cudaGetSymbolAddress((void**)&elo,  g_elo);

    cudaFuncSetAttribute(gemm_mma_k<EPI_BIAS>,
                         cudaFuncAttributeMaxDynamicSharedMemorySize, 65536);
    cudaFuncSetAttribute(gemm_mma_k<EPI_BIAS_RES>,
                         cudaFuncAttributeMaxDynamicSharedMemorySize, 65536);
    cudaFuncSetAttribute(gemm_mma_k<EPI_BIAS_GELU>,
                         cudaFuncAttributeMaxDynamicSharedMemorySize, 65536);

    const dim3 wtb(32, 8);
    const dim3 g512(16, 16);                  // 512x512 weight transpose
    const dim3 gP(DMODEL / 128, TKN / 128);   // [4096,512] gemms: 4 x 32
    const dim3 gF1(DFF / 128, TKN / 128);     // FF1: 16 x 32
    const dim3 gA(NSEQ / 64, NHEAD, BATCH);   // attention: 32 x 8 x 2

    // ---- weight transpose+split (once per launch) ----
    cvt_wt_k<<<g512, wtb>>>(m_wq, whi + OFF_MWQ, wlo + OFF_MWQ, 512, 512);
    cvt_wt_k<<<g512, wtb>>>(m_wk, whi + OFF_MWK, wlo + OFF_MWK, 512, 512);
    cvt_wt_k<<<g512, wtb>>>(m_wv, whi + OFF_MWV, wlo + OFF_MWV, 512, 512);
    cvt_wt_k<<<g512, wtb>>>(m_wo, whi + OFF_MWO, wlo + OFF_MWO, 512, 512);
    cvt_wt_k<<<g512, wtb>>>(c_wq, whi + OFF_CWQ, wlo + OFF_CWQ, 512, 512);
    cvt_wt_k<<<g512, wtb>>>(c_wk, whi + OFF_CWK, wlo + OFF_CWK, 512, 512);
    cvt_wt_k<<<g512, wtb>>>(c_wv, whi + OFF_CWV, wlo + OFF_CWV, 512, 512);
    cvt_wt_k<<<g512, wtb>>>(c_wo, whi + OFF_CWO, wlo + OFF_CWO, 512, 512);
    cvt_wt_k<<<dim3(64, 16), wtb>>>(ff_w1, whi + OFF_FF1, wlo + OFF_FF1, 512, 2048);
    cvt_wt_k<<<dim3(16, 64), wtb>>>(ff_w2, whi + OFF_FF2, wlo + OFF_FF2, 2048, 512);
    cvt_act_k<<<2048, 256>>>(enc, ehi, elo, TKN * DMODEL / 4);

    // ---- masked self-attention ----
    cvt_act_k<<<2048, 256>>>(x, ahi, alo, TKN * DMODEL / 4);
    gemm_mma_k<EPI_BIAS><<<gP, 256, 65536>>>(ahi, alo, whi + OFF_MWQ, wlo + OFF_MWQ, m_bq, nullptr, q, DMODEL, DMODEL);
    gemm_mma_k<EPI_BIAS><<<gP, 256, 65536>>>(ahi, alo, whi + OFF_MWK, wlo + OFF_MWK, m_bk, nullptr, k, DMODEL, DMODEL);
    gemm_mma_k<EPI_BIAS><<<gP, 256, 65536>>>(ahi, alo, whi + OFF_MWV, wlo + OFF_MWV, m_bv, nullptr, v, DMODEL, DMODEL);
    flash2_k<true><<<gA, 256>>>(q, k, v, attn);
    cvt_act_k<<<2048, 256>>>(attn, ahi, alo, TKN * DMODEL / 4);
    gemm_mma_k<EPI_BIAS_RES><<<gP, 256, 65536>>>(ahi, alo, whi + OFF_MWO, wlo + OFF_MWO, m_bo, x, t0, DMODEL, DMODEL);
    ln_k<<<TKN, 128>>>(t0, ln1_g, ln1_b, x1);

    // ---- cross-attention ----
    cvt_act_k<<<2048, 256>>>(x1, ahi, alo, TKN * DMODEL / 4);
    gemm_mma_k<EPI_BIAS><<<gP, 256, 65536>>>(ahi, alo, whi + OFF_CWQ, wlo + OFF_CWQ, c_bq, nullptr, q, DMODEL, DMODEL);
    gemm_mma_k<EPI_BIAS><<<gP, 256, 65536>>>(ehi, elo, whi + OFF_CWK, wlo + OFF_CWK, c_bk, nullptr, k, DMODEL, DMODEL);
    gemm_mma_k<EPI_BIAS><<<gP, 256, 65536>>>(ehi, elo, whi + OFF_CWV, wlo + OFF_CWV, c_bv, nullptr, v, DMODEL, DMODEL);
    flash2_k<false><<<gA, 256>>>(q, k, v, attn);
    cvt_act_k<<<2048, 256>>>(attn, ahi, alo, TKN * DMODEL / 4);
    gemm_mma_k<EPI_BIAS_RES><<<gP, 256, 65536>>>(ahi, alo, whi + OFF_CWO, wlo + OFF_CWO, c_bo, x1, t0, DMODEL, DMODEL);
    ln_k<<<TKN, 128>>>(t0, ln2_g, ln2_b, x2);

    // ---- feed-forward ----
    cvt_act_k<<<2048, 256>>>(x2, ahi, alo, TKN * DMODEL / 4);
    gemm_mma_k<EPI_BIAS_GELU><<<gF1, 256, 65536>>>(ahi, alo, whi + OFF_FF1, wlo + OFF_FF1, ff_b1, nullptr, ff, DFF, DMODEL);
    cvt_act_k<<<8192, 256>>>(ff, ahi, alo, TKN * DFF / 4);
    gemm_mma_k<EPI_BIAS_RES><<<gP, 256, 65536>>>(ahi, alo, whi + OFF_FF2, wlo + OFF_FF2, ff_b2, x2, t0, DMODEL, DFF);
    ln_k<<<TKN, 128>>>(t0, ln3_g, ln3_b, (float*)d_out);
}

// round 12
// speedup vs baseline: 3.3802x; 1.8648x over previous
#include <cuda_runtime.h>
#include <cuda_bf16.h>
#include <math.h>
#include <stdint.h>

// ---------------------------------------------------------------------------
// Decoder layer: B=2, N=2048, D=512, H=8, Dh=64, FF=2048.
// Linear GEMMs AND flash attention on HMMA (mma.sync bf16, 3-term split =
// fp32-accurate emulation). sm_103 baseline PTX only (no tcgen05).
// ---------------------------------------------------------------------------

#define NSEQ   2048
#define BATCH  2
#define DMODEL 512
#define NHEAD  8
#define DHEAD  64
#define DFF    2048
#define TKN    (BATCH * NSEQ)

typedef unsigned long long ull;

// ---------------- device scratch (no allocations allowed) ------------------
__device__ float g_q   [TKN * DMODEL];
__device__ float g_k   [TKN * DMODEL];
__device__ float g_v   [TKN * DMODEL];
__device__ float g_attn[TKN * DMODEL];
__device__ float g_t0  [TKN * DMODEL];
__device__ float g_x1  [TKN * DMODEL];
__device__ float g_x2  [TKN * DMODEL];
__device__ float g_ff  [TKN * DFF];

// bf16 split buffers
__device__ __nv_bfloat16 g_whi[4194304];
__device__ __nv_bfloat16 g_wlo[4194304];
__device__ __nv_bfloat16 g_ahi[TKN * DFF];
__device__ __nv_bfloat16 g_alo[TKN * DFF];
__device__ __nv_bfloat16 g_ehi[TKN * DMODEL];
__device__ __nv_bfloat16 g_elo[TKN * DMODEL];

#define OFF_MWQ 0
#define OFF_MWK 262144
#define OFF_MWV 524288
#define OFF_MWO 786432
#define OFF_CWQ 1048576
#define OFF_CWK 1310720
#define OFF_CWV 1572864
#define OFF_CWO 1835008
#define OFF_FF1 2097152
#define OFF_FF2 3145728

enum { EPI_BIAS = 0, EPI_BIAS_RES = 1, EPI_BIAS_GELU = 2 };

// ---------------- PTX helpers ----------------------------------------------
__device__ __forceinline__ uint32_t smem_u32(const void* p) {
    uint32_t a;
    asm("{ .reg .u64 t; cvta.to.shared.u64 t, %1; cvt.u32.u64 %0, t; }"
        : "=r"(a) : "l"(p));
    return a;
}
__device__ __forceinline__ void ldm_x4(uint32_t* r, uint32_t addr) {
    asm volatile("ldmatrix.sync.aligned.m8n8.x4.shared.b16 {%0,%1,%2,%3}, [%4];"
                 : "=r"(r[0]), "=r"(r[1]), "=r"(r[2]), "=r"(r[3]) : "r"(addr));
}
__device__ __forceinline__ void ldm_x4_t(uint32_t* r, uint32_t addr) {
    asm volatile("ldmatrix.sync.aligned.m8n8.x4.trans.shared.b16 {%0,%1,%2,%3}, [%4];"
                 : "=r"(r[0]), "=r"(r[1]), "=r"(r[2]), "=r"(r[3]) : "r"(addr));
}
__device__ __forceinline__ void mma16816(float* c, const uint32_t* a,
                                         uint32_t b0, uint32_t b1) {
    asm volatile(
        "mma.sync.aligned.m16n8k16.row.col.f32.bf16.bf16.f32 "
        "{%0,%1,%2,%3}, {%4,%5,%6,%7}, {%8,%9}, {%0,%1,%2,%3};"
        : "+f"(c[0]), "+f"(c[1]), "+f"(c[2]), "+f"(c[3])
        : "r"(a[0]), "r"(a[1]), "r"(a[2]), "r"(a[3]), "r"(b0), "r"(b1));
}
// pack two fp32 -> bf16x2; lower 16 bits = 'lo_elem' (even col), upper = 'hi_elem'
__device__ __forceinline__ uint32_t bf16x2_pack(float hi_elem, float lo_elem) {
    uint32_t r;
    asm("cvt.rn.bf16x2.f32 %0, %1, %2;" : "=r"(r) : "f"(hi_elem), "f"(lo_elem));
    return r;
}
// pack 4 fp32 -> 2 bf16x2 in a ull: elements in ascending memory order
__device__ __forceinline__ ull bf16x4_pack(float4 v) {
    uint32_t a = bf16x2_pack(v.y, v.x);
    uint32_t b = bf16x2_pack(v.w, v.z);
    return (ull)a | ((ull)b << 32);
}

// ---------------------------------------------------------------------------
// Conversion kernels: fp32 -> bf16 hi + bf16 lo (lo = round(x - hi))
// ---------------------------------------------------------------------------
__global__ void __launch_bounds__(256)
cvt_act_k(const float* __restrict__ x, __nv_bfloat16* __restrict__ hi,
          __nv_bfloat16* __restrict__ lo, int n4)
{
    int i = blockIdx.x * 256 + threadIdx.x;
    if (i >= n4) return;
    float4 v = ((const float4*)x)[i];
    float f[4] = { v.x, v.y, v.z, v.w };
    ushort4 hv, lv;
    unsigned short* hp = &hv.x;
    unsigned short* lp = &lv.x;
#pragma unroll
    for (int t = 0; t < 4; t++) {
        __nv_bfloat16 h = __float2bfloat16(f[t]);
        __nv_bfloat16 l = __float2bfloat16(f[t] - __bfloat162float(h));
        hp[t] = __bfloat16_as_ushort(h);
        lp[t] = __bfloat16_as_ushort(l);
    }
    ((ushort4*)hi)[i] = hv;
    ((ushort4*)lo)[i] = lv;
}

__global__ void __launch_bounds__(256)
cvt_wt_k(const float* __restrict__ W, __nv_bfloat16* __restrict__ hi,
         __nv_bfloat16* __restrict__ lo, int K, int N)
{
    __shared__ float t[32][33];
    const int n0 = blockIdx.x * 32, k0 = blockIdx.y * 32;
    const int tx = threadIdx.x, ty = threadIdx.y;
#pragma unroll
    for (int i = 0; i < 32; i += 8)
        t[ty + i][tx] = W[(size_t)(k0 + ty + i) * N + n0 + tx];
    __syncthreads();
#pragma unroll
    for (int i = 0; i < 32; i += 8) {
        float v = t[tx][ty + i];
        __nv_bfloat16 h = __float2bfloat16(v);
        __nv_bfloat16 l = __float2bfloat16(v - __bfloat162float(h));
        size_t o = (size_t)(n0 + ty + i) * K + k0 + tx;
        hi[o] = h;
        lo[o] = l;
    }
}

// ---------------------------------------------------------------------------
// HMMA GEMM (unchanged from R10 passing kernel).
// ---------------------------------------------------------------------------
template<int EPI>
__global__ void __launch_bounds__(256)
gemm_mma_k(const __nv_bfloat16* __restrict__ a_hi, const __nv_bfloat16* __restrict__ a_lo,
           const __nv_bfloat16* __restrict__ b_hi, const __nv_bfloat16* __restrict__ b_lo,
           const float* __restrict__ bias, const float* __restrict__ res,
           float* __restrict__ C, int N, int K)
{
    extern __shared__ __align__(128) char dsm[];

    const int tid  = threadIdx.x;
    const int wid  = tid >> 5;
    const int lane = tid & 31;
    const int m0 = blockIdx.y * 128;
    const int n0 = blockIdx.x * 128;
    const int wm = (wid & 1) * 64;
    const int wn = (wid >> 1) * 32;

    const uint32_t sb  = smem_u32(dsm);
    const uint32_t sAh = sb;
    const uint32_t sAl = sb + 16384u;
    const uint32_t sBh = sb + 32768u;
    const uint32_t sBl = sb + 49152u;

    float acc[4][4][4];
#pragma unroll
    for (int mi = 0; mi < 4; mi++)
#pragma unroll
        for (int nj = 0; nj < 4; nj++)
#pragma unroll
            for (int r = 0; r < 4; r++) acc[mi][nj][r] = 0.0f;

    const int nch = K >> 6;
    for (int ch = 0; ch < nch; ch++) {
        if (ch > 0) __syncthreads();
        const int k0 = ch * 64;
#pragma unroll
        for (int i = 0; i < 4; i++) {
            int l = tid + i * 256;
            int r = l >> 3;
            int c = l & 7;
            uint32_t soff = (uint32_t)(r * 128 + ((c ^ (r & 7)) << 4));
            size_t goA = (size_t)(m0 + r) * K + k0 + c * 8;
            size_t goB = (size_t)(n0 + r) * K + k0 + c * 8;
            *(uint4*)(dsm + soff)           = *(const uint4*)(a_hi + goA);
            *(uint4*)(dsm + 16384 + soff)   = *(const uint4*)(a_lo + goA);
            *(uint4*)(dsm + 32768 + soff)   = *(const uint4*)(b_hi + goB);
            *(uint4*)(dsm + 49152 + soff)   = *(const uint4*)(b_lo + goB);
        }
        __syncthreads();

#pragma unroll
        for (int ks = 0; ks < 4; ks++) {
            uint32_t Bh[2][4], Bl[2][4];
#pragma unroll
            for (int np = 0; np < 2; np++) {
                int brow = wn + np * 16 + (lane & 7) + ((lane >> 4) & 1) * 8;
                int bcu  = ks * 2 + ((lane >> 3) & 1);
                uint32_t ba = (uint32_t)(brow * 128 + ((bcu ^ (brow & 7)) << 4));
                ldm_x4(Bh[np], sBh + ba);
                ldm_x4(Bl[np], sBl + ba);
            }
#pragma unroll
            for (int mi = 0; mi < 4; mi++) {
                int arow = wm + mi * 16 + (lane & 15);
                int acu  = ks * 2 + (lane >> 4);
                uint32_t aa = (uint32_t)(arow * 128 + ((acu ^ (arow & 7)) << 4));
                uint32_t Ah[4], Al[4];
                ldm_x4(Ah, sAh + aa);
                ldm_x4(Al, sAl + aa);
#pragma unroll
                for (int nj = 0; nj < 4; nj++) {
                    const int np = nj >> 1, s = (nj & 1) * 2;
                    mma16816(acc[mi][nj], Ah, Bh[np][s], Bh[np][s + 1]);
                    mma16816(acc[mi][nj], Ah, Bl[np][s], Bl[np][s + 1]);
                    mma16816(acc[mi][nj], Al, Bh[np][s], Bh[np][s + 1]);
                }
            }
        }
    }

#pragma unroll
    for (int mi = 0; mi < 4; mi++) {
#pragma unroll
        for (int nj = 0; nj < 4; nj++) {
            size_t row = (size_t)m0 + wm + mi * 16 + (lane >> 2);
            size_t col = (size_t)n0 + wn + nj * 8 + (lane & 3) * 2;
            float b0 = bias[col], b1 = bias[col + 1];
#pragma unroll
            for (int h = 0; h < 2; h++) {
                size_t rw = row + h * 8;
                float o0 = acc[mi][nj][h * 2 + 0] + b0;
                float o1 = acc[mi][nj][h * 2 + 1] + b1;
                if (EPI == EPI_BIAS_GELU) {
                    o0 = 0.5f * o0 * (1.0f + erff(o0 * 0.70710678118654752f));
                    o1 = 0.5f * o1 * (1.0f + erff(o1 * 0.70710678118654752f));
                }
                if (EPI == EPI_BIAS_RES) {
                    float2 rv = *(const float2*)(res + rw * N + col);
                    o0 += rv.x; o1 += rv.y;
                }
                *(float2*)(C + rw * N + col) = make_float2(o0, o1);
            }
        }
    }
}

// ---------------------------------------------------------------------------
// Flash attention on HMMA, 3-term bf16 split for QK^T and PV.
// Block: 64 q-rows of one (b,h); 128 threads = 4 warps x 16 q-rows.
// Smem (dynamic 48KB): Qh Ql Kh Kl Vh Vl, each [64][64] bf16, XOR-swizzled
// per 16B unit (unit ^ (row&7)). V stays [kv][d]; consumed via ldmatrix.trans.
// S accumulators live in mma C-layout; softmax via quad-lane shfl; P frags
// rebuilt in registers (cvt.rn.bf16x2.f32), P_lo = p - float(p_hi).
// ---------------------------------------------------------------------------
template<bool CAUSAL>
__global__ void __launch_bounds__(128)
flash_mma_k(const float* __restrict__ Q, const float* __restrict__ K,
            const float* __restrict__ V, float* __restrict__ O)
{
    extern __shared__ __align__(128) char fsm[];
    const uint32_t sb  = smem_u32(fsm);
    const uint32_t sQh = sb;
    const uint32_t sQl = sb + 8192u;
    const uint32_t sKh = sb + 16384u;
    const uint32_t sKl = sb + 24576u;
    const uint32_t sVh = sb + 32768u;
    const uint32_t sVl = sb + 40960u;

    const int tid  = threadIdx.x;
    const int wid  = tid >> 5;
    const int lane = tid & 31;
    const int qb   = blockIdx.x;
    const int h    = blockIdx.y;
    const int b    = blockIdx.z;
    const size_t base = (size_t)b * NSEQ * DMODEL + (size_t)h * DHEAD;

    // ---- load Q tile (64x64) fp32 -> bf16 hi/lo swizzled ----
#pragma unroll
    for (int it = 0; it < 8; it++) {
        int l = tid + it * 128;
        int r = l >> 4, t = l & 15;
        float4 v = *(const float4*)(Q + base + (size_t)(qb * 64 + r) * DMODEL + t * 4);
        float4 hv, lv;
        hv.x = __bfloat162float(__float2bfloat16(v.x)); lv.x = v.x - hv.x;
        hv.y = __bfloat162float(__float2bfloat16(v.y)); lv.y = v.y - hv.y;
        hv.z = __bfloat162float(__float2bfloat16(v.z)); lv.z = v.z - hv.z;
        hv.w = __bfloat162float(__float2bfloat16(v.w)); lv.w = v.w - hv.w;
        int unit = t >> 1, half = t & 1;
        uint32_t off = (uint32_t)(r * 128 + ((unit ^ (r & 7)) << 4) + half * 8);
        *(ull*)(fsm + off)        = bf16x4_pack(hv);
        *(ull*)(fsm + 8192 + off) = bf16x4_pack(lv);
    }

    float m_i[2] = { -INFINITY, -INFINITY };
    float l_i[2] = { 0.0f, 0.0f };
    float oa[8][4];
#pragma unroll
    for (int nj = 0; nj < 8; nj++)
#pragma unroll
        for (int r = 0; r < 4; r++) oa[nj][r] = 0.0f;

    const int nkt = CAUSAL ? (qb + 1) : (NSEQ / 64);

    for (int kt = 0; kt < nkt; kt++) {
        __syncthreads();   // prior reads of K/V done; Q stores visible (iter 0)
        // ---- load K, V tiles fp32 -> bf16 hi/lo swizzled ----
#pragma unroll
        for (int it = 0; it < 8; it++) {
            int l = tid + it * 128;
            int r = l >> 4, t = l & 15;
            size_t go = base + (size_t)(kt * 64 + r) * DMODEL + t * 4;
            int unit = t >> 1, half = t & 1;
            uint32_t off = (uint32_t)(r * 128 + ((unit ^ (r & 7)) << 4) + half * 8);
            float4 kv = *(const float4*)(K + go);
            float4 hv, lv;
            hv.x = __bfloat162float(__float2bfloat16(kv.x)); lv.x = kv.x - hv.x;
            hv.y = __bfloat162float(__float2bfloat16(kv.y)); lv.y = kv.y - hv.y;
            hv.z = __bfloat162float(__float2bfloat16(kv.z)); lv.z = kv.z - hv.z;
            hv.w = __bfloat162float(__float2bfloat16(kv.w)); lv.w = kv.w - hv.w;
            *(ull*)(fsm + 16384 + off) = bf16x4_pack(hv);
            *(ull*)(fsm + 24576 + off) = bf16x4_pack(lv);
            float4 vv = *(const float4*)(V + go);
            hv.x = __bfloat162float(__float2bfloat16(vv.x)); lv.x = vv.x - hv.x;
            hv.y = __bfloat162float(__float2bfloat16(vv.y)); lv.y = vv.y - hv.y;
            hv.z = __bfloat162float(__float2bfloat16(vv.z)); lv.z = vv.z - hv.z;
            hv.w = __bfloat162float(__float2bfloat16(vv.w)); lv.w = vv.w - hv.w;
            *(ull*)(fsm + 32768 + off) = bf16x4_pack(hv);
            *(ull*)(fsm + 40960 + off) = bf16x4_pack(lv);
        }
        __syncthreads();

        // ---- S = Q K^T (M=16/warp, N=64 kpos, K=64 d) ----
        float sa[8][4];
#pragma unroll
        for (int nj = 0; nj < 8; nj++)
#pragma unroll
            for (int r = 0; r < 4; r++) sa[nj][r] = 0.0f;

#pragma unroll
        for (int ks = 0; ks < 4; ks++) {
            int arow = wid * 16 + (lane & 15);
            int acu  = ks * 2 + (lane >> 4);
            uint32_t aa = (uint32_t)(arow * 128 + ((acu ^ (arow & 7)) << 4));
            uint32_t Qh[4], Ql[4];
            ldm_x4(Qh, sQh + aa);
            ldm_x4(Ql, sQl + aa);
#pragma unroll
            for (int np = 0; np < 4; np++) {
                int brow = np * 16 + (lane & 7) + ((lane >> 4) & 1) * 8;
                int bcu  = ks * 2 + ((lane >> 3) & 1);
                uint32_t ba = (uint32_t)(brow * 128 + ((bcu ^ (brow & 7)) << 4));
                uint32_t Kh[4], Kl[4];
                ldm_x4(Kh, sKh + ba);
                ldm_x4(Kl, sKl + ba);
#pragma unroll
                for (int hf = 0; hf < 2; hf++) {
                    const int nj = np * 2 + hf, s = hf * 2;
                    mma16816(sa[nj], Qh, Kh[s], Kh[s + 1]);
                    mma16816(sa[nj], Qh, Kl[s], Kl[s + 1]);
                    mma16816(sa[nj], Ql, Kh[s], Kh[s + 1]);
                }
            }
        }

        // ---- softmax (C-layout; rows lane>>2 and +8; quad-lane reductions) ----
#pragma unroll
        for (int i = 0; i < 2; i++) {
            const int qg = qb * 64 + wid * 16 + (lane >> 2) + i * 8;
            float mx = -INFINITY;
#pragma unroll
            for (int nj = 0; nj < 8; nj++) {
#pragma unroll
                for (int jj = 0; jj < 2; jj++) {
                    float sv = sa[nj][i * 2 + jj] * 0.125f;
                    if (CAUSAL && (kt * 64 + nj * 8 + (lane & 3) * 2 + jj > qg))
                        sv = -INFINITY;
                    sa[nj][i * 2 + jj] = sv;
                    mx = fmaxf(mx, sv);
                }
            }
            mx = fmaxf(mx, __shfl_xor_sync(0xffffffffu, mx, 1));
            mx = fmaxf(mx, __shfl_xor_sync(0xffffffffu, mx, 2));
            float mnew  = fmaxf(m_i[i], mx);
            float alpha = __expf(m_i[i] - mnew);
            float rs = 0.0f;
#pragma unroll
            for (int nj = 0; nj < 8; nj++) {
#pragma unroll
                for (int jj = 0; jj < 2; jj++) {
                    float e = __expf(sa[nj][i * 2 + jj] - mnew);
                    sa[nj][i * 2 + jj] = e;
                    rs += e;
                }
            }
            rs += __shfl_xor_sync(0xffffffffu, rs, 1);
            rs += __shfl_xor_sync(0xffffffffu, rs, 2);
            l_i[i] = l_i[i] * alpha + rs;
            m_i[i] = mnew;
#pragma unroll
            for (int nj = 0; nj < 8; nj++) {
                oa[nj][i * 2 + 0] *= alpha;
                oa[nj][i * 2 + 1] *= alpha;
            }
        }

        // ---- O += P V (A = P from registers, B = V via ldmatrix.trans) ----
#pragma unroll
        for (int kk = 0; kk < 4; kk++) {
            uint32_t Ph[4], Pl[4];
#pragma unroll
            for (int u = 0; u < 4; u++) {          // u: {tile even/odd} x {row lo/hi}
                const int nj = kk * 2 + (u >> 1);
                const int ri = (u & 1) * 2;        // c0c1 or c2c3
                float p0 = sa[nj][ri + 0], p1 = sa[nj][ri + 1];
                uint32_t hpair = bf16x2_pack(p1, p0);
                float h0 = __uint_as_float(hpair << 16);
                float h1 = __uint_as_float(hpair & 0xffff0000u);
                // A-frag order: a0=(row,klo) a1=(row+8,klo) a2=(row,khi) a3=(row+8,khi)
                const int ai = (u & 1) + (u >> 1) * 2;
                Ph[ai] = hpair;
                Pl[ai] = bf16x2_pack(p1 - h1, p0 - h0);
            }
#pragma unroll
            for (int dp = 0; dp < 4; dp++) {
                int krow = kk * 16 + (lane & 7) + ((lane >> 3) & 1) * 8;
                int unit = dp * 2 + (lane >> 4);
                uint32_t va = (uint32_t)(krow * 128 + ((unit ^ (krow & 7)) << 4));
                uint32_t Vh[4], Vl[4];
                ldm_x4_t(Vh, sVh + va);
                ldm_x4_t(Vl, sVl + va);
#pragma unroll
                for (int hf = 0; hf < 2; hf++) {
                    const int nj = dp * 2 + hf, s = hf * 2;
                    mma16816(oa[nj], Ph, Vh[s], Vh[s + 1]);
                    mma16816(oa[nj], Ph, Vl[s], Vl[s + 1]);
                    mma16816(oa[nj], Pl, Vh[s], Vh[s + 1]);
                }
            }
        }
    }

    // ---- write normalized output ----
    float inv0 = 1.0f / l_i[0], inv1 = 1.0f / l_i[1];
#pragma unroll
    for (int nj = 0; nj < 8; nj++) {
        int d = nj * 8 + (lane & 3) * 2;
        int q0 = qb * 64 + wid * 16 + (lane >> 2);
        *(float2*)(O + base + (size_t)q0 * DMODEL + d) =
            make_float2(oa[nj][0] * inv0, oa[nj][1] * inv0);
        *(float2*)(O + base + (size_t)(q0 + 8) * DMODEL + d) =
            make_float2(oa[nj][2] * inv1, oa[nj][3] * inv1);
    }
}

// ---------------------------------------------------------------------------
// LayerNorm over last dim (512). One block (128 threads) per token row.
// ---------------------------------------------------------------------------
__global__ void __launch_bounds__(128)
ln_k(const float* __restrict__ x, const float* __restrict__ gamma,
     const float* __restrict__ beta, float* __restrict__ out)
{
    __shared__ float red[8];
    const int row = blockIdx.x;
    const int t = threadIdx.x;
    const float* xr = x + (size_t)row * DMODEL;

    float4 v = *(const float4*)(xr + t * 4);
    float s = v.x + v.y + v.z + v.w;
    float q = v.x * v.x + v.y * v.y + v.z * v.z + v.w * v.w;
#pragma unroll
    for (int off = 16; off > 0; off >>= 1) {
        s += __shfl_xor_sync(0xffffffffu, s, off);
        q += __shfl_xor_sync(0xffffffffu, q, off);
    }
    int w = t >> 5;
    if ((t & 31) == 0) { red[w] = s; red[4 + w] = q; }
    __syncthreads();
    s = red[0] + red[1] + red[2] + red[3];
    q = red[4] + red[5] + red[6] + red[7];

    float mu  = s * (1.0f / DMODEL);
    float var = q * (1.0f / DMODEL) - mu * mu;
    float inv = rsqrtf(var + 1e-5f);

    float4 gg = *(const float4*)(gamma + t * 4);
    float4 bb = *(const float4*)(beta  + t * 4);
    float4 o;
    o.x = (v.x - mu) * inv * gg.x + bb.x;
    o.y = (v.y - mu) * inv * gg.y + bb.y;
    o.z = (v.z - mu) * inv * gg.z + bb.z;
    o.w = (v.w - mu) * inv * gg.w + bb.w;
    *(float4*)(out + (size_t)row * DMODEL + t * 4) = o;
}

// ---------------------------------------------------------------------------
extern "C" void kernel_launch(void* const* d_in, const int* in_sizes, int n_in,
                              void* d_out, int out_size)
{
    const float* x     = (const float*)d_in[0];
    const float* enc   = (const float*)d_in[1];
    const float* m_wq  = (const float*)d_in[2];
    const float* m_bq  = (const float*)d_in[3];
    const float* m_wk  = (const float*)d_in[4];
    const float* m_bk  = (const float*)d_in[5];
    const float* m_wv  = (const float*)d_in[6];
    const float* m_bv  = (const float*)d_in[7];
    const float* m_wo  = (const float*)d_in[8];
    const float* m_bo  = (const float*)d_in[9];
    const float* c_wq  = (const float*)d_in[10];
    const float* c_bq  = (const float*)d_in[11];
    const float* c_wk  = (const float*)d_in[12];
    const float* c_bk  = (const float*)d_in[13];
    const float* c_wv  = (const float*)d_in[14];
    const float* c_bv  = (const float*)d_in[15];
    const float* c_wo  = (const float*)d_in[16];
    const float* c_bo  = (const float*)d_in[17];
    const float* ln1_g = (const float*)d_in[18];
    const float* ln1_b = (const float*)d_in[19];
    const float* ln2_g = (const float*)d_in[20];
    const float* ln2_b = (const float*)d_in[21];
    const float* ln3_g = (const float*)d_in[22];
    const float* ln3_b = (const float*)d_in[23];
    const float* ff_w1 = (const float*)d_in[24];
    const float* ff_b1 = (const float*)d_in[25];
    const float* ff_w2 = (const float*)d_in[26];
    const float* ff_b2 = (const float*)d_in[27];

    float *q, *k, *v, *attn, *t0, *x1, *x2, *ff;
    __nv_bfloat16 *whi, *wlo, *ahi, *alo, *ehi, *elo;
    cudaGetSymbolAddress((void**)&q,    g_q);
    cudaGetSymbolAddress((void**)&k,    g_k);
    cudaGetSymbolAddress((void**)&v,    g_v);
    cudaGetSymbolAddress((void**)&attn, g_attn);
    cudaGetSymbolAddress((void**)&t0,   g_t0);
    cudaGetSymbolAddress((void**)&x1,   g_x1);
    cudaGetSymbolAddress((void**)&x2,   g_x2);
    cudaGetSymbolAddress((void**)&ff,   g_ff);
    cudaGetSymbolAddress((void**)&whi,  g_whi);
    cudaGetSymbolAddress((void**)&wlo,  g_wlo);
    cudaGetSymbolAddress((void**)&ahi,  g_ahi);
    cudaGetSymbolAddress((void**)&alo,  g_alo);
    cudaGetSymbolAddress((void**)&ehi,  g_ehi);
    cudaGetSymbolAddress((void**)&elo,  g_elo);

    cudaFuncSetAttribute(gemm_mma_k<EPI_BIAS>,
                         cudaFuncAttributeMaxDynamicSharedMemorySize, 65536);
    cudaFuncSetAttribute(gemm_mma_k<EPI_BIAS_RES>,
                         cudaFuncAttributeMaxDynamicSharedMemorySize, 65536);
    cudaFuncSetAttribute(gemm_mma_k<EPI_BIAS_GELU>,
                         cudaFuncAttributeMaxDynamicSharedMemorySize, 65536);
    cudaFuncSetAttribute(flash_mma_k<true>,
                         cudaFuncAttributeMaxDynamicSharedMemorySize, 49152);
    cudaFuncSetAttribute(flash_mma_k<false>,
                         cudaFuncAttributeMaxDynamicSharedMemorySize, 49152);

    const dim3 wtb(32, 8);
    const dim3 g512(16, 16);
    const dim3 gP(DMODEL / 128, TKN / 128);
    const dim3 gF1(DFF / 128, TKN / 128);
    const dim3 gA(NSEQ / 64, NHEAD, BATCH);

    // ---- weight transpose+split ----
    cvt_wt_k<<<g512, wtb>>>(m_wq, whi + OFF_MWQ, wlo + OFF_MWQ, 512, 512);
    cvt_wt_k<<<g512, wtb>>>(m_wk, whi + OFF_MWK, wlo + OFF_MWK, 512, 512);
    cvt_wt_k<<<g512, wtb>>>(m_wv, whi + OFF_MWV, wlo + OFF_MWV, 512, 512);
    cvt_wt_k<<<g512, wtb>>>(m_wo, whi + OFF_MWO, wlo + OFF_MWO, 512, 512);
    cvt_wt_k<<<g512, wtb>>>(c_wq, whi + OFF_CWQ, wlo + OFF_CWQ, 512, 512);
    cvt_wt_k<<<g512, wtb>>>(c_wk, whi + OFF_CWK, wlo + OFF_CWK, 512, 512);
    cvt_wt_k<<<g512, wtb>>>(c_wv, whi + OFF_CWV, wlo + OFF_CWV, 512, 512);
    cvt_wt_k<<<g512, wtb>>>(c_wo, whi + OFF_CWO, wlo + OFF_CWO, 512, 512);
    cvt_wt_k<<<dim3(64, 16), wtb>>>(ff_w1, whi + OFF_FF1, wlo + OFF_FF1, 512, 2048);
    cvt_wt_k<<<dim3(16, 64), wtb>>>(ff_w2, whi + OFF_FF2, wlo + OFF_FF2, 2048, 512);
    cvt_act_k<<<2048, 256>>>(enc, ehi, elo, TKN * DMODEL / 4);

    // ---- masked self-attention ----
    cvt_act_k<<<2048, 256>>>(x, ahi, alo, TKN * DMODEL / 4);
    gemm_mma_k<EPI_BIAS><<<gP, 256, 65536>>>(ahi, alo, whi + OFF_MWQ, wlo + OFF_MWQ, m_bq, nullptr, q, DMODEL, DMODEL);
    gemm_mma_k<EPI_BIAS><<<gP, 256, 65536>>>(ahi, alo, whi + OFF_MWK, wlo + OFF_MWK, m_bk, nullptr, k, DMODEL, DMODEL);
    gemm_mma_k<EPI_BIAS><<<gP, 256, 65536>>>(ahi, alo, whi + OFF_MWV, wlo + OFF_MWV, m_bv, nullptr, v, DMODEL, DMODEL);
    flash_mma_k<true><<<gA, 128, 49152>>>(q, k, v, attn);
    cvt_act_k<<<2048, 256>>>(attn, ahi, alo, TKN * DMODEL / 4);
    gemm_mma_k<EPI_BIAS_RES><<<gP, 256, 65536>>>(ahi, alo, whi + OFF_MWO, wlo + OFF_MWO, m_bo, x, t0, DMODEL, DMODEL);
    ln_k<<<TKN, 128>>>(t0, ln1_g, ln1_b, x1);

    // ---- cross-attention ----
    cvt_act_k<<<2048, 256>>>(x1, ahi, alo, TKN * DMODEL / 4);
    gemm_mma_k<EPI_BIAS><<<gP, 256, 65536>>>(ahi, alo, whi + OFF_CWQ, wlo + OFF_CWQ, c_bq, nullptr, q, DMODEL, DMODEL);
    gemm_mma_k<EPI_BIAS><<<gP, 256, 65536>>>(ehi, elo, whi + OFF_CWK, wlo + OFF_CWK, c_bk, nullptr, k, DMODEL, DMODEL);
    gemm_mma_k<EPI_BIAS><<<gP, 256, 65536>>>(ehi, elo, whi + OFF_CWV, wlo + OFF_CWV, c_bv, nullptr, v, DMODEL, DMODEL);
    flash_mma_k<false><<<gA, 128, 49152>>>(q, k, v, attn);
    cvt_act_k<<<2048, 256>>>(attn, ahi, alo, TKN * DMODEL / 4);
    gemm_mma_k<EPI_BIAS_RES><<<gP, 256, 65536>>>(ahi, alo, whi + OFF_CWO, wlo + OFF_CWO, c_bo, x1, t0, DMODEL, DMODEL);
    ln_k<<<TKN, 128>>>(t0, ln2_g, ln2_b, x2);

    // ---- feed-forward ----
    cvt_act_k<<<2048, 256>>>(x2, ahi, alo, TKN * DMODEL / 4);
    gemm_mma_k<EPI_BIAS_GELU><<<gF1, 256, 65536>>>(ahi, alo, whi + OFF_FF1, wlo + OFF_FF1, ff_b1, nullptr, ff, DFF, DMODEL);
    cvt_act_k<<<8192, 256>>>(ff, ahi, alo, TKN * DFF / 4);
    gemm_mma_k<EPI_BIAS_RES><<<gP, 256, 65536>>>(ahi, alo, whi + OFF_FF2, wlo + OFF_FF2, ff_b2, x2, t0, DMODEL, DFF);
    ln_k<<<TKN, 128>>>(t0, ln3_g, ln3_b, (float*)d_out);
}

// round 15
// speedup vs baseline: 3.4357x; 1.0164x over previous
#include <cuda_runtime.h>
#include <cuda_bf16.h>
#include <math.h>
#include <stdint.h>

// ---------------------------------------------------------------------------
// Decoder layer: B=2, N=2048, D=512, H=8, Dh=64, FF=2048.
// Linear GEMMs AND flash attention on HMMA (mma.sync bf16, 3-term split =
// fp32-accurate emulation). Fused dataflow: GEMM/flash/LN epilogues emit
// bf16 hi/lo split operands directly; no intermediate fp32 round-trips.
// ---------------------------------------------------------------------------

#define NSEQ   2048
#define BATCH  2
#define DMODEL 512
#define NHEAD  8
#define DHEAD  64
#define DFF    2048
#define TKN    (BATCH * NSEQ)

typedef unsigned long long ull;

// ---------------- device scratch (no allocations allowed) ------------------
__device__ float g_t0 [TKN * DMODEL];
__device__ float g_x1 [TKN * DMODEL];
__device__ float g_x2 [TKN * DMODEL];

// bf16 split buffers
__device__ __nv_bfloat16 g_whi [4194304];        // transposed weights, hi
__device__ __nv_bfloat16 g_wlo [4194304];        // transposed weights, lo
__device__ __nv_bfloat16 g_ffhi[TKN * DFF];      // FF1 output hi
__device__ __nv_bfloat16 g_fflo[TKN * DFF];      // FF1 output lo
__device__ __nv_bfloat16 g_xhi [TKN * DMODEL];
__device__ __nv_bfloat16 g_xlo [TKN * DMODEL];
__device__ __nv_bfloat16 g_ehi [TKN * DMODEL];
__device__ __nv_bfloat16 g_elo [TKN * DMODEL];
__device__ __nv_bfloat16 g_qhi [TKN * DMODEL];
__device__ __nv_bfloat16 g_qlo [TKN * DMODEL];
__device__ __nv_bfloat16 g_khi [TKN * DMODEL];
__device__ __nv_bfloat16 g_klo [TKN * DMODEL];
__device__ __nv_bfloat16 g_vhi [TKN * DMODEL];
__device__ __nv_bfloat16 g_vlo [TKN * DMODEL];
__device__ __nv_bfloat16 g_athi[TKN * DMODEL];
__device__ __nv_bfloat16 g_atlo[TKN * DMODEL];
__device__ __nv_bfloat16 g_x1hi[TKN * DMODEL];
__device__ __nv_bfloat16 g_x1lo[TKN * DMODEL];
__device__ __nv_bfloat16 g_x2hi[TKN * DMODEL];
__device__ __nv_bfloat16 g_x2lo[TKN * DMODEL];

#define OFF_MWQ 0
#define OFF_MWK 262144
#define OFF_MWV 524288
#define OFF_MWO 786432
#define OFF_CWQ 1048576
#define OFF_CWK 1310720
#define OFF_CWV 1572864
#define OFF_CWO 1835008
#define OFF_FF1 2097152
#define OFF_FF2 3145728

enum { EPI_BIAS = 0, EPI_BIAS_RES = 1, EPI_BIAS_GELU = 2 };
enum { OUT_F32 = 0, OUT_HILO = 1 };

// ---------------- PTX helpers ----------------------------------------------
__device__ __forceinline__ uint32_t smem_u32(const void* p) {
    uint32_t a;
    asm("{ .reg .u64 t; cvta.to.shared.u64 t, %1; cvt.u32.u64 %0, t; }"
        : "=r"(a) : "l"(p));
    return a;
}
__device__ __forceinline__ void ldm_x4(uint32_t* r, uint32_t addr) {
    asm volatile("ldmatrix.sync.aligned.m8n8.x4.shared.b16 {%0,%1,%2,%3}, [%4];"
                 : "=r"(r[0]), "=r"(r[1]), "=r"(r[2]), "=r"(r[3]) : "r"(addr));
}
__device__ __forceinline__ void ldm_x4_t(uint32_t* r, uint32_t addr) {
    asm volatile("ldmatrix.sync.aligned.m8n8.x4.trans.shared.b16 {%0,%1,%2,%3}, [%4];"
                 : "=r"(r[0]), "=r"(r[1]), "=r"(r[2]), "=r"(r[3]) : "r"(addr));
}
__device__ __forceinline__ void mma16816(float* c, const uint32_t* a,
                                         uint32_t b0, uint32_t b1) {
    asm volatile(
        "mma.sync.aligned.m16n8k16.row.col.f32.bf16.bf16.f32 "
        "{%0,%1,%2,%3}, {%4,%5,%6,%7}, {%8,%9}, {%0,%1,%2,%3};"
        : "+f"(c[0]), "+f"(c[1]), "+f"(c[2]), "+f"(c[3])
        : "r"(a[0]), "r"(a[1]), "r"(a[2]), "r"(a[3]), "r"(b0), "r"(b1));
}
// pack two fp32 -> bf16x2; lower 16 bits = 'lo_elem' (even col), upper = 'hi_elem'
__device__ __forceinline__ uint32_t bf16x2_pack(float hi_elem, float lo_elem) {
    uint32_t r;
    asm("cvt.rn.bf16x2.f32 %0, %1, %2;" : "=r"(r) : "f"(hi_elem), "f"(lo_elem));
    return r;
}
// split (o0,o1) into hi-pair + lo-pair (packed bf16x2 each)
__device__ __forceinline__ void hilo_pair(float o0, float o1,
                                          uint32_t& hp, uint32_t& lp) {
    hp = bf16x2_pack(o1, o0);
    float h0 = __uint_as_float(hp << 16);
    float h1 = __uint_as_float(hp & 0xffff0000u);
    lp = bf16x2_pack(o1 - h1, o0 - h0);
}

// ---------------------------------------------------------------------------
// Input conversion: fp32 -> bf16 hi + bf16 lo (only for graph inputs x, enc)
// ---------------------------------------------------------------------------
__global__ void __launch_bounds__(256)
cvt_act_k(const float* __restrict__ x, __nv_bfloat16* __restrict__ hi,
          __nv_bfloat16* __restrict__ lo, int n4)
{
    int i = blockIdx.x * 256 + threadIdx.x;
    if (i >= n4) return;
    float4 v = ((const float4*)x)[i];
    uint32_t h0, l0, h1, l1;
    hilo_pair(v.x, v.y, h0, l0);
    hilo_pair(v.z, v.w, h1, l1);
    ((uint2*)hi)[i] = make_uint2(h0, h1);
    ((uint2*)lo)[i] = make_uint2(l0, l1);
}

// W[K,N] fp32 -> Wt_hi/lo[N,K] bf16 (transpose + split), 32x32 smem tiles
__global__ void __launch_bounds__(256)
cvt_wt_k(const float* __restrict__ W, __nv_bfloat16* __restrict__ hi,
         __nv_bfloat16* __restrict__ lo, int K, int N)
{
    __shared__ float t[32][33];
    const int n0 = blockIdx.x * 32, k0 = blockIdx.y * 32;
    const int tx = threadIdx.x, ty = threadIdx.y;
#pragma unroll
    for (int i = 0; i < 32; i += 8)
        t[ty + i][tx] = W[(size_t)(k0 + ty + i) * N + n0 + tx];
    __syncthreads();
#pragma unroll
    for (int i = 0; i < 32; i += 8) {
        float v = t[tx][ty + i];
        __nv_bfloat16 h = __float2bfloat16(v);
        __nv_bfloat16 l = __float2bfloat16(v - __bfloat162float(h));
        size_t o = (size_t)(n0 + ty + i) * K + k0 + tx;
        hi[o] = h;
        lo[o] = l;
    }
}

// ---------------------------------------------------------------------------
// HMMA GEMM: C = A @ Wt^T + bias (+res / gelu); output fp32 or bf16 hi/lo.
// Mainloop identical to R12 passing kernel.
// ---------------------------------------------------------------------------
template<int EPI, int OUT>
__global__ void __launch_bounds__(256)
gemm_mma_k(const __nv_bfloat16* __restrict__ a_hi, const __nv_bfloat16* __restrict__ a_lo,
           const __nv_bfloat16* __restrict__ b_hi, const __nv_bfloat16* __restrict__ b_lo,
           const float* __restrict__ bias, const float* __restrict__ res,
           float* __restrict__ C, __nv_bfloat16* __restrict__ Chi,
           __nv_bfloat16* __restrict__ Clo, int N, int K)
{
    extern __shared__ __align__(128) char dsm[];

    const int tid  = threadIdx.x;
    const int wid  = tid >> 5;
    const int lane = tid & 31;
    const int m0 = blockIdx.y * 128;
    const int n0 = blockIdx.x * 128;
    const int wm = (wid & 1) * 64;
    const int wn = (wid >> 1) * 32;

    const uint32_t sb  = smem_u32(dsm);
    const uint32_t sAh = sb;
    const uint32_t sAl = sb + 16384u;
    const uint32_t sBh = sb + 32768u;
    const uint32_t sBl = sb + 49152u;

    float acc[4][4][4];
#pragma unroll
    for (int mi = 0; mi < 4; mi++)
#pragma unroll
        for (int nj = 0; nj < 4; nj++)
#pragma unroll
            for (int r = 0; r < 4; r++) acc[mi][nj][r] = 0.0f;

    const int nch = K >> 6;
    for (int ch = 0; ch < nch; ch++) {
        if (ch > 0) __syncthreads();
        const int k0 = ch * 64;
#pragma unroll
        for (int i = 0; i < 4; i++) {
            int l = tid + i * 256;
            int r = l >> 3;
            int c = l & 7;
            uint32_t soff = (uint32_t)(r * 128 + ((c ^ (r & 7)) << 4));
            size_t goA = (size_t)(m0 + r) * K + k0 + c * 8;
            size_t goB = (size_t)(n0 + r) * K + k0 + c * 8;
            *(uint4*)(dsm + soff)           = *(const uint4*)(a_hi + goA);
            *(uint4*)(dsm + 16384 + soff)   = *(const uint4*)(a_lo + goA);
            *(uint4*)(dsm + 32768 + soff)   = *(const uint4*)(b_hi + goB);
            *(uint4*)(dsm + 49152 + soff)   = *(const uint4*)(b_lo + goB);
        }
        __syncthreads();

#pragma unroll
        for (int ks = 0; ks < 4; ks++) {
            uint32_t Bh[2][4], Bl[2][4];
#pragma unroll
            for (int np = 0; np < 2; np++) {
                int brow = wn + np * 16 + (lane & 7) + ((lane >> 4) & 1) * 8;
                int bcu  = ks * 2 + ((lane >> 3) & 1);
                uint32_t ba = (uint32_t)(brow * 128 + ((bcu ^ (brow & 7)) << 4));
                ldm_x4(Bh[np], sBh + ba);
                ldm_x4(Bl[np], sBl + ba);
            }
#pragma unroll
            for (int mi = 0; mi < 4; mi++) {
                int arow = wm + mi * 16 + (lane & 15);
                int acu  = ks * 2 + (lane >> 4);
                uint32_t aa = (uint32_t)(arow * 128 + ((acu ^ (arow & 7)) << 4));
                uint32_t Ah[4], Al[4];
                ldm_x4(Ah, sAh + aa);
                ldm_x4(Al, sAl + aa);
#pragma unroll
                for (int nj = 0; nj < 4; nj++) {
                    const int np = nj >> 1, s = (nj & 1) * 2;
                    mma16816(acc[mi][nj], Ah, Bh[np][s], Bh[np][s + 1]);
                    mma16816(acc[mi][nj], Ah, Bl[np][s], Bl[np][s + 1]);
                    mma16816(acc[mi][nj], Al, Bh[np][s], Bh[np][s + 1]);
                }
            }
        }
    }

#pragma unroll
    for (int mi = 0; mi < 4; mi++) {
#pragma unroll
        for (int nj = 0; nj < 4; nj++) {
            size_t row = (size_t)m0 + wm + mi * 16 + (lane >> 2);
            size_t col = (size_t)n0 + wn + nj * 8 + (lane & 3) * 2;
            float b0 = bias[col], b1 = bias[col + 1];
#pragma unroll
            for (int h = 0; h < 2; h++) {
                size_t rw = row + h * 8;
                float o0 = acc[mi][nj][h * 2 + 0] + b0;
                float o1 = acc[mi][nj][h * 2 + 1] + b1;
                if (EPI == EPI_BIAS_GELU) {
                    o0 = 0.5f * o0 * (1.0f + erff(o0 * 0.70710678118654752f));
                    o1 = 0.5f * o1 * (1.0f + erff(o1 * 0.70710678118654752f));
                }
                if (EPI == EPI_BIAS_RES) {
                    float2 rv = *(const float2*)(res + rw * N + col);
                    o0 += rv.x; o1 += rv.y;
                }
                if (OUT == OUT_F32) {
                    *(float2*)(C + rw * N + col) = make_float2(o0, o1);
                } else {
                    uint32_t hp, lp;
                    hilo_pair(o0, o1, hp, lp);
                    *(uint32_t*)(Chi + rw * N + col) = hp;
                    *(uint32_t*)(Clo + rw * N + col) = lp;
                }
            }
        }
    }
}

// ---------------------------------------------------------------------------
// Flash attention on HMMA, 3-term bf16 split. Inputs are PRE-SPLIT bf16 hi/lo
// (same [b,n,h*64+d] layout, stride DMODEL); smem fill = pure swizzled uint4
// copies. Output written as bf16 hi/lo for the O-projection GEMM.
// Fragment logic identical to R12 passing kernel. Smem 48KB.
// ---------------------------------------------------------------------------
template<bool CAUSAL>
__global__ void __launch_bounds__(128)
flash_mma_k(const __nv_bfloat16* __restrict__ Qhi, const __nv_bfloat16* __restrict__ Qlo,
            const __nv_bfloat16* __restrict__ Khi, const __nv_bfloat16* __restrict__ Klo,
            const __nv_bfloat16* __restrict__ Vhi, const __nv_bfloat16* __restrict__ Vlo,
            __nv_bfloat16* __restrict__ Ohi, __nv_bfloat16* __restrict__ Olo)
{
    extern __shared__ __align__(128) char fsm[];
    const uint32_t sb  = smem_u32(fsm);
    const uint32_t sQh = sb;
    const uint32_t sQl = sb + 8192u;
    const uint32_t sKh = sb + 16384u;
    const uint32_t sKl = sb + 24576u;
    const uint32_t sVh = sb + 32768u;
    const uint32_t sVl = sb + 40960u;

    const int tid  = threadIdx.x;
    const int wid  = tid >> 5;
    const int lane = tid & 31;
    const int qb   = blockIdx.x;
    const int h    = blockIdx.y;
    const int b    = blockIdx.z;
    const size_t base = (size_t)b * NSEQ * DMODEL + (size_t)h * DHEAD;

    // ---- load Q tile (64x64 bf16 hi/lo), swizzled uint4 copy ----
#pragma unroll
    for (int it = 0; it < 4; it++) {
        int l = tid + it * 128;
        int r = l >> 3, c = l & 7;
        uint32_t off = (uint32_t)(r * 128 + ((c ^ (r & 7)) << 4));
        size_t go = base + (size_t)(qb * 64 + r) * DMODEL + c * 8;
        *(uint4*)(fsm + off)        = *(const uint4*)(Qhi + go);
        *(uint4*)(fsm + 8192 + off) = *(const uint4*)(Qlo + go);
    }

    float m_i[2] = { -INFINITY, -INFINITY };
    float l_i[2] = { 0.0f, 0.0f };
    float oa[8][4];
#pragma unroll
    for (int nj = 0; nj < 8; nj++)
#pragma unroll
        for (int r = 0; r < 4; r++) oa[nj][r] = 0.0f;

    const int nkt = CAUSAL ? (qb + 1) : (NSEQ / 64);

    for (int kt = 0; kt < nkt; kt++) {
        __syncthreads();   // prior reads of K/V done; Q stores visible (iter 0)
        // ---- load K, V tiles (bf16 hi/lo), swizzled uint4 copies ----
#pragma unroll
        for (int it = 0; it < 4; it++) {
            int l = tid + it * 128;
            int r = l >> 3, c = l & 7;
            uint32_t off = (uint32_t)(r * 128 + ((c ^ (r & 7)) << 4));
            size_t go = base + (size_t)(kt * 64 + r) * DMODEL + c * 8;
            *(uint4*)(fsm + 16384 + off) = *(const uint4*)(Khi + go);
            *(uint4*)(fsm + 24576 + off) = *(const uint4*)(Klo + go);
            *(uint4*)(fsm + 32768 + off) = *(const uint4*)(Vhi + go);
            *(uint4*)(fsm + 40960 + off) = *(const uint4*)(Vlo + go);
        }
        __syncthreads();

        // ---- S = Q K^T (M=16/warp, N=64 kpos, K=64 d) ----
        float sa[8][4];
#pragma unroll
        for (int nj = 0; nj < 8; nj++)
#pragma unroll
            for (int r = 0; r < 4; r++) sa[nj][r] = 0.0f;

#pragma unroll
        for (int ks = 0; ks < 4; ks++) {
            int arow = wid * 16 + (lane & 15);
            int acu  = ks * 2 + (lane >> 4);
            uint32_t aa = (uint32_t)(arow * 128 + ((acu ^ (arow & 7)) << 4));
            uint32_t Qh[4], Ql[4];
            ldm_x4(Qh, sQh + aa);
            ldm_x4(Ql, sQl + aa);
#pragma unroll
            for (int np = 0; np < 4; np++) {
                int brow = np * 16 + (lane & 7) + ((lane >> 4) & 1) * 8;
                int bcu  = ks * 2 + ((lane >> 3) & 1);
                uint32_t ba = (uint32_t)(brow * 128 + ((bcu ^ (brow & 7)) << 4));
                uint32_t Kh[4], Kl[4];
                ldm_x4(Kh, sKh + ba);
                ldm_x4(Kl, sKl + ba);
#pragma unroll
                for (int hf = 0; hf < 2; hf++) {
                    const int nj = np * 2 + hf, s = hf * 2;
                    mma16816(sa[nj], Qh, Kh[s], Kh[s + 1]);
                    mma16816(sa[nj], Qh, Kl[s], Kl[s + 1]);
                    mma16816(sa[nj], Ql, Kh[s], Kh[s + 1]);
                }
            }
        }

        // ---- softmax (C-layout; rows lane>>2 and +8; quad-lane reductions) ----
#pragma unroll
        for (int i = 0; i < 2; i++) {
            const int qg = qb * 64 + wid * 16 + (lane >> 2) + i * 8;
            float mx = -INFINITY;
#pragma unroll
            for (int nj = 0; nj < 8; nj++) {
#pragma unroll
                for (int jj = 0; jj < 2; jj++) {
                    float sv = sa[nj][i * 2 + jj] * 0.125f;
                    if (CAUSAL && (kt * 64 + nj * 8 + (lane & 3) * 2 + jj > qg))
                        sv = -INFINITY;
                    sa[nj][i * 2 + jj] = sv;
                    mx = fmaxf(mx, sv);
                }
            }
            mx = fmaxf(mx, __shfl_xor_sync(0xffffffffu, mx, 1));
            mx = fmaxf(mx, __shfl_xor_sync(0xffffffffu, mx, 2));
            float mnew  = fmaxf(m_i[i], mx);
            float alpha = __expf(m_i[i] - mnew);
            float rs = 0.0f;
#pragma unroll
            for (int nj = 0; nj < 8; nj++) {
#pragma unroll
                for (int jj = 0; jj < 2; jj++) {
                    float e = __expf(sa[nj][i * 2 + jj] - mnew);
                    sa[nj][i * 2 + jj] = e;
                    rs += e;
                }
            }
            rs += __shfl_xor_sync(0xffffffffu, rs, 1);
            rs += __shfl_xor_sync(0xffffffffu, rs, 2);
            l_i[i] = l_i[i] * alpha + rs;
            m_i[i] = mnew;
#pragma unroll
            for (int nj = 0; nj < 8; nj++) {
                oa[nj][i * 2 + 0] *= alpha;
                oa[nj][i * 2 + 1] *= alpha;
            }
        }

        // ---- O += P V (A = P from registers, B = V via ldmatrix.trans) ----
#pragma unroll
        for (int kk = 0; kk < 4; kk++) {
            uint32_t Ph[4], Pl[4];
#pragma unroll
            for (int u = 0; u < 4; u++) {          // u: {tile even/odd} x {row lo/hi}
                const int nj = kk * 2 + (u >> 1);
                const int ri = (u & 1) * 2;        // c0c1 or c2c3
                float p0 = sa[nj][ri + 0], p1 = sa[nj][ri + 1];
                uint32_t hpair, lpair;
                hilo_pair(p0, p1, hpair, lpair);
                // A-frag order: a0=(row,klo) a1=(row+8,klo) a2=(row,khi) a3=(row+8,khi)
                const int ai = (u & 1) + (u >> 1) * 2;
                Ph[ai] = hpair;
                Pl[ai] = lpair;
            }
#pragma unroll
            for (int dp = 0; dp < 4; dp++) {
                int krow = kk * 16 + (lane & 7) + ((lane >> 3) & 1) * 8;
                int unit = dp * 2 + (lane >> 4);
                uint32_t va = (uint32_t)(krow * 128 + ((unit ^ (krow & 7)) << 4));
                uint32_t Vh[4], Vl[4];
                ldm_x4_t(Vh, sVh + va);
                ldm_x4_t(Vl, sVl + va);
#pragma unroll
                for (int hf = 0; hf < 2; hf++) {
                    const int nj = dp * 2 + hf, s = hf * 2;
                    mma16816(oa[nj], Ph, Vh[s], Vh[s + 1]);
                    mma16816(oa[nj], Ph, Vl[s], Vl[s + 1]);
                    mma16816(oa[nj], Pl, Vh[s], Vh[s + 1]);
                }
            }
        }
    }

    // ---- write normalized output as bf16 hi/lo ----
    float inv0 = 1.0f / l_i[0], inv1 = 1.0f / l_i[1];
#pragma unroll
    for (int nj = 0; nj < 8; nj++) {
        int d = nj * 8 + (lane & 3) * 2;
        int q0 = qb * 64 + wid * 16 + (lane >> 2);
        uint32_t hp, lp;
        hilo_pair(oa[nj][0] * inv0, oa[nj][1] * inv0, hp, lp);
        *(uint32_t*)(Ohi + base + (size_t)q0 * DMODEL + d) = hp;
        *(uint32_t*)(Olo + base + (size_t)q0 * DMODEL + d) = lp;
        hilo_pair(oa[nj][2] * inv1, oa[nj][3] * inv1, hp, lp);
        *(uint32_t*)(Ohi + base + (size_t)(q0 + 8) * DMODEL + d) = hp;
        *(uint32_t*)(Olo + base + (size_t)(q0 + 8) * DMODEL + d) = lp;
    }
}

// ---------------------------------------------------------------------------
// LayerNorm over last dim (512); optionally also emits bf16 hi/lo split.
// ---------------------------------------------------------------------------
template<bool HILO>
__global__ void __launch_bounds__(128)
ln_k(const float* __restrict__ x, const float* __restrict__ gamma,
     const float* __restrict__ beta, float* __restrict__ out,
     __nv_bfloat16* __restrict__ hi, __nv_bfloat16* __restrict__ lo)
{
    __shared__ float red[8];
    const int row = blockIdx.x;
    const int t = threadIdx.x;
    const float* xr = x + (size_t)row * DMODEL;

    float4 v = *(const float4*)(xr + t * 4);
    float s = v.x + v.y + v.z + v.w;
    float q = v.x * v.x + v.y * v.y + v.z * v.z + v.w * v.w;
#pragma unroll
    for (int off = 16; off > 0; off >>= 1) {
        s += __shfl_xor_sync(0xffffffffu, s, off);
        q += __shfl_xor_sync(0xffffffffu, q, off);
    }
    int w = t >> 5;
    if ((t & 31) == 0) { red[w] = s; red[4 + w] = q; }
    __syncthreads();
    s = red[0] + red[1] + red[2] + red[3];
    q = red[4] + red[5] + red[6] + red[7];

    float mu  = s * (1.0f / DMODEL);
    float var = q * (1.0f / DMODEL) - mu * mu;
    float inv = rsqrtf(var + 1e-5f);

    float4 gg = *(const float4*)(gamma + t * 4);
    float4 bb = *(const float4*)(beta  + t * 4);
    float4 o;
    o.x = (v.x - mu) * inv * gg.x + bb.x;
    o.y = (v.y - mu) * inv * gg.y + bb.y;
    o.z = (v.z - mu) * inv * gg.z + bb.z;
    o.w = (v.w - mu) * inv * gg.w + bb.w;
    *(float4*)(out + (size_t)row * DMODEL + t * 4) = o;
    if (HILO) {
        uint32_t h0, l0, h1, l1;
        hilo_pair(o.x, o.y, h0, l0);
        hilo_pair(o.z, o.w, h1, l1);
        *(uint2*)(hi + (size_t)row * DMODEL + t * 4) = make_uint2(h0, h1);
        *(uint2*)(lo + (size_t)row * DMODEL + t * 4) = make_uint2(l0, l1);
    }
}

// ---------------------------------------------------------------------------
extern "C" void kernel_launch(void* const* d_in, const int* in_sizes, int n_in,
                              void* d_out, int out_size)
{
    const float* x     = (const float*)d_in[0];
    const float* enc   = (const float*)d_in[1];
    const float* m_wq  = (const float*)d_in[2];
    const float* m_bq  = (const float*)d_in[3];
    const float* m_wk  = (const float*)d_in[4];
    const float* m_bk  = (const float*)d_in[5];
    const float* m_wv  = (const float*)d_in[6];
    const float* m_bv  = (const float*)d_in[7];
    const float* m_wo  = (const float*)d_in[8];
    const float* m_bo  = (const float*)d_in[9];
    const float* c_wq  = (const float*)d_in[10];
    const float* c_bq  = (const float*)d_in[11];
    const float* c_wk  = (const float*)d_in[12];
    const float* c_bk  = (const float*)d_in[13];
    const float* c_wv  = (const float*)d_in[14];
    const float* c_bv  = (const float*)d_in[15];
    const float* c_wo  = (const float*)d_in[16];
    const float* c_bo  = (const float*)d_in[17];
    const float* ln1_g = (const float*)d_in[18];
    const float* ln1_b = (const float*)d_in[19];
    const float* ln2_g = (const float*)d_in[20];
    const float* ln2_b = (const float*)d_in[21];
    const float* ln3_g = (const float*)d_in[22];
    const float* ln3_b = (const float*)d_in[23];
    const float* ff_w1 = (const float*)d_in[24];
    const float* ff_b1 = (const float*)d_in[25];
    const float* ff_w2 = (const float*)d_in[26];
    const float* ff_b2 = (const float*)d_in[27];

    float *t0, *x1, *x2;
    __nv_bfloat16 *whi, *wlo, *ffhi, *fflo, *xhi, *xlo, *ehi, *elo;
    __nv_bfloat16 *qhi, *qlo, *khi, *klo, *vhi, *vlo, *athi, *atlo;
    __nv_bfloat16 *x1hi, *x1lo, *x2hi, *x2lo;
    cudaGetSymbolAddress((void**)&t0,   g_t0);
    cudaGetSymbolAddress((void**)&x1,   g_x1);
    cudaGetSymbolAddress((void**)&x2,   g_x2);
    cudaGetSymbolAddress((void**)&whi,  g_whi);
    cudaGetSymbolAddress((void**)&wlo,  g_wlo);
    cudaGetSymbolAddress((void**)&ffhi, g_ffhi);
    cudaGetSymbolAddress((void**)&fflo, g_fflo);
    cudaGetSymbolAddress((void**)&xhi,  g_xhi);
    cudaGetSymbolAddress((void**)&xlo,  g_xlo);
    cudaGetSymbolAddress((void**)&ehi,  g_ehi);
    cudaGetSymbolAddress((void**)&elo,  g_elo);
    cudaGetSymbolAddress((void**)&qhi,  g_qhi);
    cudaGetSymbolAddress((void**)&qlo,  g_qlo);
    cudaGetSymbolAddress((void**)&khi,  g_khi);
    cudaGetSymbolAddress((void**)&klo,  g_klo);
    cudaGetSymbolAddress((void**)&vhi,  g_vhi);
    cudaGetSymbolAddress((void**)&vlo,  g_vlo);
    cudaGetSymbolAddress((void**)&athi, g_athi);
    cudaGetSymbolAddress((void**)&atlo, g_atlo);
    cudaGetSymbolAddress((void**)&x1hi, g_x1hi);
    cudaGetSymbolAddress((void**)&x1lo, g_x1lo);
    cudaGetSymbolAddress((void**)&x2hi, g_x2hi);
    cudaGetSymbolAddress((void**)&x2lo, g_x2lo);

    cudaFuncSetAttribute(gemm_mma_k<EPI_BIAS, OUT_HILO>,
                         cudaFuncAttributeMaxDynamicSharedMemorySize, 65536);
    cudaFuncSetAttribute(gemm_mma_k<EPI_BIAS_RES, OUT_F32>,
                         cudaFuncAttributeMaxDynamicSharedMemorySize, 65536);
    cudaFuncSetAttribute(gemm_mma_k<EPI_BIAS_GELU, OUT_HILO>,
                         cudaFuncAttributeMaxDynamicSharedMemorySize, 65536);
    cudaFuncSetAttribute(flash_mma_k<true>,
                         cudaFuncAttributeMaxDynamicSharedMemorySize, 49152);
    cudaFuncSetAttribute(flash_mma_k<false>,
                         cudaFuncAttributeMaxDynamicSharedMemorySize, 49152);

    const dim3 wtb(32, 8);
    const dim3 g512(16, 16);
    const dim3 gP(DMODEL / 128, TKN / 128);
    const dim3 gF1(DFF / 128, TKN / 128);
    const dim3 gA(NSEQ / 64, NHEAD, BATCH);

    // ---- weight transpose+split + input conversions ----
    cvt_wt_k<<<g512, wtb>>>(m_wq, whi + OFF_MWQ, wlo + OFF_MWQ, 512, 512);
    cvt_wt_k<<<g512, wtb>>>(m_wk, whi + OFF_MWK, wlo + OFF_MWK, 512, 512);
    cvt_wt_k<<<g512, wtb>>>(m_wv, whi + OFF_MWV, wlo + OFF_MWV, 512, 512);
    cvt_wt_k<<<g512, wtb>>>(m_wo, whi + OFF_MWO, wlo + OFF_MWO, 512, 512);
    cvt_wt_k<<<g512, wtb>>>(c_wq, whi + OFF_CWQ, wlo + OFF_CWQ, 512, 512);
    cvt_wt_k<<<g512, wtb>>>(c_wk, whi + OFF_CWK, wlo + OFF_CWK, 512, 512);
    cvt_wt_k<<<g512, wtb>>>(c_wv, whi + OFF_CWV, wlo + OFF_CWV, 512, 512);
    cvt_wt_k<<<g512, wtb>>>(c_wo, whi + OFF_CWO, wlo + OFF_CWO, 512, 512);
    cvt_wt_k<<<dim3(64, 16), wtb>>>(ff_w1, whi + OFF_FF1, wlo + OFF_FF1, 512, 2048);
    cvt_wt_k<<<dim3(16, 64), wtb>>>(ff_w2, whi + OFF_FF2, wlo + OFF_FF2, 2048, 512);
    cvt_act_k<<<2048, 256>>>(x,   xhi, xlo, TKN * DMODEL / 4);
    cvt_act_k<<<2048, 256>>>(enc, ehi, elo, TKN * DMODEL / 4);

    // ---- masked self-attention ----
    gemm_mma_k<EPI_BIAS, OUT_HILO><<<gP, 256, 65536>>>(xhi, xlo, whi + OFF_MWQ, wlo + OFF_MWQ, m_bq, nullptr, nullptr, qhi, qlo, DMODEL, DMODEL);
    gemm_mma_k<EPI_BIAS, OUT_HILO><<<gP, 256, 65536>>>(xhi, xlo, whi + OFF_MWK, wlo + OFF_MWK, m_bk, nullptr, nullptr, khi, klo, DMODEL, DMODEL);
    gemm_mma_k<EPI_BIAS, OUT_HILO><<<gP, 256, 65536>>>(xhi, xlo, whi + OFF_MWV, wlo + OFF_MWV, m_bv, nullptr, nullptr, vhi, vlo, DMODEL, DMODEL);
    flash_mma_k<true><<<gA, 128, 49152>>>(qhi, qlo, khi, klo, vhi, vlo, athi, atlo);
    gemm_mma_k<EPI_BIAS_RES, OUT_F32><<<gP, 256, 65536>>>(athi, atlo, whi + OFF_MWO, wlo + OFF_MWO, m_bo, x, t0, nullptr, nullptr, DMODEL, DMODEL);
    ln_k<true><<<TKN, 128>>>(t0, ln1_g, ln1_b, x1, x1hi, x1lo);

    // ---- cross-attention ----
    gemm_mma_k<EPI_BIAS, OUT_HILO><<<gP, 256, 65536>>>(x1hi, x1lo, whi + OFF_CWQ, wlo + OFF_CWQ, c_bq, nullptr, nullptr, qhi, qlo, DMODEL, DMODEL);
    gemm_mma_k<EPI_BIAS, OUT_HILO><<<gP, 256, 65536>>>(ehi, elo, whi + OFF_CWK, wlo + OFF_CWK, c_bk, nullptr, nullptr, khi, klo, DMODEL, DMODEL);
    gemm_mma_k<EPI_BIAS, OUT_HILO><<<gP, 256, 65536>>>(ehi, elo, whi + OFF_CWV, wlo + OFF_CWV, c_bv, nullptr, nullptr, vhi, vlo, DMODEL, DMODEL);
    flash_mma_k<false><<<gA, 128, 49152>>>(qhi, qlo, khi, klo, vhi, vlo, athi, atlo);
    gemm_mma_k<EPI_BIAS_RES, OUT_F32><<<gP, 256, 65536>>>(athi, atlo, whi + OFF_CWO, wlo + OFF_CWO, c_bo, x1, t0, nullptr, nullptr, DMODEL, DMODEL);
    ln_k<true><<<TKN, 128>>>(t0, ln2_g, ln2_b, x2, x2hi, x2lo);

    // ---- feed-forward ----
    gemm_mma_k<EPI_BIAS_GELU, OUT_HILO><<<gF1, 256, 65536>>>(x2hi, x2lo, whi + OFF_FF1, wlo + OFF_FF1, ff_b1, nullptr, nullptr, ffhi, fflo, DFF, DMODEL);
    gemm_mma_k<EPI_BIAS_RES, OUT_F32><<<gP, 256, 65536>>>(ffhi, fflo, whi + OFF_FF2, wlo + OFF_FF2, ff_b2, x2, t0, nullptr, nullptr, DMODEL, DFF);
    ln_k<false><<<TKN, 128>>>(t0, ln3_g, ln3_b, (float*)d_out, nullptr, nullptr);
}